// round 10
// baseline (speedup 1.0000x reference)
#include <cuda_runtime.h>
#include <cstdint>

#define N_ANCH   100800
#define D_COLS   117
#define NC       80
#define NM       32
#define TOPK     4096
#define MAX_DET  300
#define CONF_T   0.25f
#define IOU_T    0.45f
#define CAND_CAP 8192
#define NWORDS   128            // TOPK/32
#define MBLK     148
#define MTHR     512
#define MTOT     (MBLK * MTHR)  // 75776
#define MWARPS   (MBLK * 16)    // 2368
#define TROWS    64             // rows per P0 tile
#define TF4      ((TROWS * D_COLS) / 4)   // 1872 float4 per tile
#define NTILE    (N_ANCH / TROWS)         // 1575

// ---------------- scratch (static __device__ — no allocation) ----------------
__device__ float              g_score[N_ANCH];
__device__ float              g_cls[N_ANCH];
__device__ unsigned int       g_hist[65536];          // zero at init; re-zeroed each run
__device__ unsigned int       g_chunk[64];            // zero at init; re-zeroed each run
__device__ unsigned int       g_thresh_bucket;
__device__ unsigned int       g_ncand;                // zero at init; reset each run
__device__ unsigned long long g_cand[CAND_CAP];
__device__ unsigned int       g_rankp[CAND_CAP];      // zero at init; reset each run
__device__ int                g_top_idx[TOPK];
__device__ float              g_top_s[TOPK];
__device__ float              g_by1[TOPK], g_bx1[TOPK], g_by2[TOPK], g_bx2[TOPK], g_bar_a[TOPK];
__device__ unsigned int       g_maskT[NWORDS * TOPK]; // [jword][row]
__device__ int                g_out_pos[MAX_DET];
__device__ unsigned char      g_out_keep[MAX_DET];

__device__ unsigned int          g_bar_count;
__device__ volatile unsigned int g_bar_gen;

// ---------------- helpers ----------------
__device__ __forceinline__ unsigned int f2key(float f) {
    unsigned int b = __float_as_uint(f);
    return b ^ ((b >> 31) ? 0xFFFFFFFFu : 0x80000000u);
}
__device__ __forceinline__ float key2f(unsigned int k) {
    unsigned int b = (k & 0x80000000u) ? (k ^ 0x80000000u) : ~k;
    return __uint_as_float(b);
}
__device__ __forceinline__ void grid_bar() {
    __syncthreads();
    if (threadIdx.x == 0) {
        unsigned int gen = g_bar_gen;
        __threadfence();
        unsigned int t = atomicAdd(&g_bar_count, 1u);
        if (t == MBLK - 1) {
            g_bar_count = 0;
            __threadfence();
            g_bar_gen = gen + 1;
        } else {
            while (g_bar_gen == gen) { }
        }
        __threadfence();
    }
    __syncthreads();
}

// ---------------- the whole pipeline, ONE launch ----------------
__global__ void __launch_bounds__(MTHR, 1) k_mega(const float* __restrict__ x,
                                                  float* __restrict__ out) {
    __shared__ float              stile[TROWS * D_COLS];   // 29952 B (P0)
    __shared__ unsigned int       s_sufg[256];
    __shared__ int                s_c, s_g;
    __shared__ unsigned int       s_rem;
    __shared__ unsigned long long s_tile[MTHR];            // 4 KB (P4)
    __shared__ float              e_y1[16][32], e_x1[16][32], e_y2[16][32], e_x2[16][32], e_ar[16][32];
    __shared__ unsigned int       s_rm[NWORDS];
    __shared__ unsigned int       s_kept[NWORDS];
    __shared__ int                s_tot[NWORDS];

    const int tid  = threadIdx.x;
    const int bid  = blockIdx.x;
    const int gid  = bid * MTHR + tid;
    const int lane = tid & 31;
    const int wid  = tid >> 5;

    // ---- P0: score/class + histogram (smem tiles, batched loads, prefetch) --
    {
        const int r = tid >> 3, e = tid & 7;               // row, eighth
        float4 v[4];
        int t = bid;
        if (t < NTILE) {
            const float4* src = (const float4*)x + (size_t)t * TF4;
#pragma unroll
            for (int k = 0; k < 4; k++) { int i = tid + k * MTHR; if (i < TF4) v[k] = src[i]; }
        }
        while (t < NTILE) {
            __syncthreads();                               // smem free from prev compute
            float4* dst4 = (float4*)stile;
#pragma unroll
            for (int k = 0; k < 4; k++) { int i = tid + k * MTHR; if (i < TF4) dst4[i] = v[k]; }
            __syncthreads();
            int tn = t + MBLK;
            if (tn < NTILE) {                              // prefetch next tile
                const float4* src = (const float4*)x + (size_t)tn * TF4;
#pragma unroll
                for (int k = 0; k < 4; k++) { int i = tid + k * MTHR; if (i < TF4) v[k] = src[i]; }
            }
            const float* row = stile + r * D_COLS;
            float obj = row[4];
            float best = -1.0f; int bc = NC;
#pragma unroll
            for (int k = 0; k < 10; k++) {
                int c = e * 10 + k;
                float p = __fmul_rn(row[5 + c], obj);
                if (p > best) { best = p; bc = c; }        // strict > : first index wins
            }
#pragma unroll
            for (int off = 1; off <= 4; off <<= 1) {
                float ov = __shfl_xor_sync(0xFFFFFFFFu, best, off);
                int   oc = __shfl_xor_sync(0xFFFFFFFFu, bc,   off);
                if (ov > best || (ov == best && oc < bc)) { best = ov; bc = oc; }
            }
            if (e == 0) {
                int ga = t * TROWS + r;
                float sc = (obj > CONF_T) ? best : -1.0f;
                g_score[ga] = sc;
                g_cls[ga]   = (float)bc;
                unsigned int key16 = f2key(sc) >> 16;
                atomicAdd(&g_hist[key16], 1u);
                atomicAdd(&g_chunk[key16 >> 10], 1u);
            }
            t = tn;
        }
    }
    grid_bar();

    // ---- P2: select threshold bucket (block 0) ----
    if (bid == 0) {
        if (tid == 0) {
            unsigned int cum = 0; int c = 0; unsigned int rem = TOPK;
            for (int b = 63; b >= 0; b--) {
                unsigned int cb = g_chunk[b];
                if (cum + cb >= TOPK) { c = b; rem = TOPK - cum; break; }
                cum += cb;
            }
            s_c = c; s_rem = rem;
        }
        __syncthreads();
        int c = s_c;
        if (tid < 256) {
            unsigned int grp = 0;
#pragma unroll
            for (int k = 0; k < 4; k++) grp += g_hist[c * 1024 + tid * 4 + k];
            s_sufg[tid] = grp;
        }
        __syncthreads();
        for (int off = 1; off < 256; off <<= 1) {
            unsigned int v = 0;
            if (tid < 256 && tid + off < 256) v = s_sufg[tid + off];
            __syncthreads();
            if (tid < 256) s_sufg[tid] += v;
            __syncthreads();
        }
        unsigned int rem = s_rem;
        if (tid < 256 && s_sufg[tid] >= rem && (tid == 255 || s_sufg[tid + 1] < rem)) s_g = tid;
        __syncthreads();
        if (tid == 0) {
            int g = s_g;
            unsigned int cum = (g == 255) ? 0u : s_sufg[g + 1];
            int T = c * 1024 + g * 4;
            for (int b = g * 4 + 3; b >= g * 4; b--) {
                cum += g_hist[c * 1024 + b];
                if (cum >= rem) { T = c * 1024 + b; break; }
            }
            g_thresh_bucket = (unsigned int)T;
        }
    }
    grid_bar();

    // ---- P3: compact candidates + re-zero hist/chunk (for next replay) ----
    {
        unsigned int tb = g_thresh_bucket;
        for (int i = gid; i < N_ANCH; i += MTOT) {
            unsigned int k = f2key(g_score[i]);
            if ((k >> 16) >= tb) {
                unsigned int pos = atomicAdd(&g_ncand, 1u);
                if (pos < CAND_CAP)
                    g_cand[pos] = ((unsigned long long)k << 32) | (unsigned int)(~i);
            }
        }
        if (gid < 65536) g_hist[gid] = 0u;       // bounds guard
        if (gid < 64)    g_chunk[gid] = 0u;
    }
    grid_bar();

    // ---- P4: segmented rank counting (blocks 0..127; 8 segments) ----
    {
        unsigned int n = g_ncand; if (n > CAND_CAP) n = CAND_CAP;
        if (bid < 128) {
            int c   = gid & (CAND_CAP - 1);
            int seg = gid >> 13;                  // 0..7
            unsigned int piece = (n + 7) >> 3;
            unsigned int lo = seg * piece;
            unsigned int hi = lo + piece; if (hi > n) hi = n;
            unsigned long long my = (c < (int)n) ? g_cand[c] : 0ULL;
            unsigned int cnt = 0;
            for (unsigned int base = lo; base < hi; base += MTHR) {
                unsigned int idx = base + tid;
                s_tile[tid] = (idx < hi) ? g_cand[idx] : 0ULL;
                __syncthreads();
                unsigned int lim = (hi - base < (unsigned)MTHR) ? (hi - base) : (unsigned)MTHR;
                for (unsigned int k = 0; k < lim; k++) cnt += (s_tile[k] > my);
                __syncthreads();
            }
            if (c < (int)n && cnt) atomicAdd(&g_rankp[c], cnt);
        }
    }
    grid_bar();

    // ---- P5: scatter into sorted order + box gather; reset counters ----
    {
        unsigned int n = g_ncand; if (n > CAND_CAP) n = CAND_CAP;
        if (gid < (int)n) {
            unsigned long long my = g_cand[gid];
            unsigned int rank = g_rankp[gid];
            g_rankp[gid] = 0u;
            if (rank < TOPK) {
                int a = (int)(~(unsigned int)my);
                g_top_s[rank]   = key2f((unsigned int)(my >> 32));
                g_top_idx[rank] = a;
                const float* row = x + (size_t)a * D_COLS;
                float xc = row[0], yc = row[1], w = row[2], h = row[3];
                float hh = __fmul_rn(h, 0.5f), hw = __fmul_rn(w, 0.5f);
                float y1 = __fsub_rn(yc, hh), x1 = __fsub_rn(xc, hw);
                float y2 = __fadd_rn(yc, hh), x2 = __fadd_rn(xc, hw);
                g_by1[rank] = y1; g_bx1[rank] = x1; g_by2[rank] = y2; g_bx2[rank] = x2;
                g_bar_a[rank] = __fmul_rn(__fsub_rn(y2, y1), __fsub_rn(x2, x1));
            }
        }
        if (gid == 0) g_ncand = 0u;
    }
    grid_bar();

    // ---- P6: dense suppression bitmask, transposed ----
    {
        int gwm = bid * 16 + wid;
        for (int g = gwm; g < 16384; g += MWARPS) {
            int rg = g >> 7;
            int w  = g & 127;
            int i  = (rg << 5) | lane;
            if (w < rg) { g_maskT[w * TOPK + i] = 0u; continue; }

            int jj = (w << 5) + lane;
            e_y1[wid][lane] = g_by1[jj]; e_x1[wid][lane] = g_bx1[jj];
            e_y2[wid][lane] = g_by2[jj]; e_x2[wid][lane] = g_bx2[jj];
            e_ar[wid][lane] = g_bar_a[jj];
            __syncwarp();

            float ry1 = g_by1[i], rx1 = g_bx1[i], ry2 = g_by2[i], rx2 = g_bx2[i];
            float rar = g_bar_a[i];
            bool  diag = (w == rg);

            unsigned int word = 0;
#pragma unroll 4
            for (int k = 0; k < 32; k++) {
                if (diag && k <= lane) continue;
                float yy1 = fmaxf(ry1, e_y1[wid][k]);
                float xx1 = fmaxf(rx1, e_x1[wid][k]);
                float yy2 = fminf(ry2, e_y2[wid][k]);
                float xx2 = fminf(rx2, e_x2[wid][k]);
                float dh  = fmaxf(__fsub_rn(yy2, yy1), 0.0f);
                float dw  = fmaxf(__fsub_rn(xx2, xx1), 0.0f);
                float it  = __fmul_rn(dh, dw);
                if (it > 0.0f) {
                    float un  = __fsub_rn(__fadd_rn(rar, e_ar[wid][k]), it);
                    float unc = fmaxf(un, 1e-9f);
                    float c   = __fmul_rn(IOU_T, unc);
                    bool  sup;
                    if (fabsf(__fsub_rn(it, c)) > 1e-4f * c) {
                        sup = (it > c);                       // far from boundary
                    } else {
                        sup = (__fdiv_rn(it, unc) > IOU_T);   // exact ref rounding
                    }
                    if (sup) word |= 1u << k;
                }
            }
            g_maskT[w * TOPK + i] = word;
            __syncwarp();
        }
    }
    grid_bar();

    // ---- P7: greedy sweep with early-stop at 300 kept (block 0) ----
    if (bid == 0) {
        bool act = tid < 128;
        unsigned int init_rm = 0, acc = 0;
        const uint4* rbase = (const uint4*)g_maskT + (size_t)(act ? tid : 0) * (TOPK / 4);
        if (act) {
#pragma unroll 4
            for (int b = 0; b < 32; b++)
                if (!(g_top_s[tid * 32 + b] > -0.5f)) init_rm |= 1u << b;
        }
        unsigned int A[32], B[32];
        if (act) {
#pragma unroll
            for (int q = 0; q < 8; q++) {
                uint4 v = rbase[q];
                A[q*4+0] = v.x; A[q*4+1] = v.y; A[q*4+2] = v.z; A[q*4+3] = v.w;
            }
        }
        __syncthreads();
        int wstop = NWORDS;
#pragma unroll 1
        for (int w = 0; w < NWORDS; w++) {
            if (act && w + 1 < NWORDS) {
#pragma unroll
                for (int q = 0; q < 8; q++) {
                    uint4 v = rbase[(w + 1) * 8 + q];
                    B[q*4+0] = v.x; B[q*4+1] = v.y; B[q*4+2] = v.z; B[q*4+3] = v.w;
                }
            }
            if (tid == w) {
                unsigned int rm = init_rm | acc;
                unsigned int kept = 0;
#pragma unroll
                for (int b = 0; b < 32; b++) {
                    if (!((rm >> b) & 1u)) { kept |= 1u << b; rm |= A[b]; }
                }
                s_rm[w] = rm; s_kept[w] = kept;
                s_tot[w] = (w ? s_tot[w - 1] : 0) + __popc(kept);   // owner-only write
            }
            __syncthreads();                       // single barrier per iteration
            if (s_tot[w] >= MAX_DET) { wstop = w + 1; break; }      // uniform decision
            if (act) {
                unsigned int kk = s_kept[w];
#pragma unroll
                for (int b = 0; b < 32; b++)
                    acc |= ((kk >> b) & 1u) ? A[b] : 0u;
#pragma unroll
                for (int b = 0; b < 32; b++) A[b] = B[b];
            }
        }
        __syncthreads();
        if (tid == 0) {            // top-300: kept first (score-desc), then pad
            int cnt = 0;
            for (int w = 0; w < wstop && cnt < MAX_DET; w++) {
                unsigned int kept = s_kept[w];
                while (kept && cnt < MAX_DET) {
                    int b = __ffs(kept) - 1; kept &= kept - 1;
                    g_out_pos[cnt] = (w << 5) | b; g_out_keep[cnt] = 1; cnt++;
                }
            }
            for (int w = 0; w < wstop && cnt < MAX_DET; w++) {      // pad (full sweep only)
                unsigned int dead = s_rm[w] & ~s_kept[w];
                dead = s_rm[w];                    // removed = suppressed or invalid
                while (dead && cnt < MAX_DET) {
                    int b = __ffs(dead) - 1; dead &= dead - 1;
                    g_out_pos[cnt] = (w << 5) | b; g_out_keep[cnt] = 0; cnt++;
                }
            }
        }
    }
    grid_bar();

    // ---- P8: final gather -> out (300 warps across blocks) ----
    {
        int gw = bid * 16 + wid;
        if (gw < MAX_DET) {
            int pos = g_out_pos[gw];
            int a   = g_top_idx[pos];
            const float* row = x + (size_t)a * D_COLS;
            if (lane == 0) {
                float xc = row[0], yc = row[1], w = row[2], h = row[3];
                float hh = __fmul_rn(h, 0.5f), hw = __fmul_rn(w, 0.5f);
                out[gw * 4 + 0] = __fsub_rn(yc, hh);
                out[gw * 4 + 1] = __fsub_rn(xc, hw);
                out[gw * 4 + 2] = __fadd_rn(yc, hh);
                out[gw * 4 + 3] = __fadd_rn(xc, hw);
                out[MAX_DET * 4 + gw] = g_cls[a];
                out[MAX_DET * 5 + gw] = g_out_keep[gw] ? g_top_s[pos] : -1.0f;
            }
            out[MAX_DET * 6 + gw * NM + lane] = row[5 + NC + lane];
        }
    }
}

// ---------------- launch ----------------
extern "C" void kernel_launch(void* const* d_in, const int* in_sizes, int n_in,
                              void* d_out, int out_size) {
    const float* x = (const float*)d_in[0];
    float* out = (float*)d_out;
    k_mega<<<MBLK, MTHR>>>(x, out);
}

// round 11
// speedup vs baseline: 1.0398x; 1.0398x over previous
#include <cuda_runtime.h>
#include <cstdint>

#define N_ANCH   100800
#define D_COLS   117
#define NC       80
#define NM       32
#define TOPK     4096
#define MAX_DET  300
#define CONF_T   0.25f
#define IOU_T    0.45f
#define CAND_CAP 8192
#define NWORDS   128            // TOPK/32
#define MBLK     148
#define MTHR     512
#define MTOT     (MBLK * MTHR)  // 75776
#define MWARPS   (MBLK * 16)    // 2368
#define SROWS    64             // rows per score block
#define SF4      ((SROWS * D_COLS) / 4)   // 1872 float4 per tile

// ---------------- scratch (static __device__ — no allocation) ----------------
__device__ float              g_score[N_ANCH];
__device__ float              g_cls[N_ANCH];
__device__ unsigned int       g_hist[65536];          // zero at init; re-zeroed each run
__device__ unsigned int       g_chunk[64];            // zero at init; re-zeroed each run
__device__ unsigned int       g_ncand;                // zero at init; reset each run
__device__ unsigned long long g_cand[CAND_CAP];
__device__ unsigned int       g_rankp[CAND_CAP];      // zero at init; reset each run
__device__ int                g_top_idx[TOPK];
__device__ float              g_top_s[TOPK];
__device__ float              g_by1[TOPK], g_bx1[TOPK], g_by2[TOPK], g_bx2[TOPK], g_bar_a[TOPK];
__device__ unsigned int       g_maskT[NWORDS * TOPK]; // [jword][row]
__device__ int                g_out_pos[MAX_DET];
__device__ unsigned char      g_out_keep[MAX_DET];

__device__ unsigned int          g_bar_count;
__device__ volatile unsigned int g_bar_gen;

// ---------------- helpers ----------------
__device__ __forceinline__ unsigned int f2key(float f) {
    unsigned int b = __float_as_uint(f);
    return b ^ ((b >> 31) ? 0xFFFFFFFFu : 0x80000000u);
}
__device__ __forceinline__ float key2f(unsigned int k) {
    unsigned int b = (k & 0x80000000u) ? (k ^ 0x80000000u) : ~k;
    return __uint_as_float(b);
}
__device__ __forceinline__ void grid_bar() {
    __syncthreads();
    if (threadIdx.x == 0) {
        unsigned int gen = g_bar_gen;
        __threadfence();
        unsigned int t = atomicAdd(&g_bar_count, 1u);
        if (t == MBLK - 1) {
            g_bar_count = 0;
            __threadfence();
            g_bar_gen = gen + 1;
        } else {
            while (g_bar_gen == gen) { }
        }
        __threadfence();
    }
    __syncthreads();
}

// ---------------- node 1: score/class + histogram (quarter-row) --------------
__global__ void __launch_bounds__(256) k_score(const float* __restrict__ x) {
    __shared__ float tile[SROWS * D_COLS];   // 29952 B
    const int bid = blockIdx.x;
    const int tid = threadIdx.x;

    // batched tile load: 8 predicated LDG.128 in flight per thread
    const float4* src = (const float4*)(x + (size_t)bid * SROWS * D_COLS);
    float4 v[8];
#pragma unroll
    for (int k = 0; k < 8; k++) {
        int i = tid + k * 256;
        if (i < SF4) v[k] = src[i];
    }
    float4* dst4 = (float4*)tile;
#pragma unroll
    for (int k = 0; k < 8; k++) {
        int i = tid + k * 256;
        if (i < SF4) dst4[i] = v[k];
    }
    __syncthreads();

    // thread = (row, quarter): 20 classes each, then 4-lane xor reduce
    const int r = tid >> 2, q = tid & 3;
    const float* row = tile + r * D_COLS;
    float obj = row[4];

    float best = -1.0f; int bc = NC;
#pragma unroll
    for (int k = 0; k < 20; k++) {
        int c = q * 20 + k;
        float p = __fmul_rn(row[5 + c], obj);
        if (p > best) { best = p; bc = c; }     // strict > : first index wins
    }
#pragma unroll
    for (int off = 1; off <= 2; off <<= 1) {
        float ov = __shfl_xor_sync(0xFFFFFFFFu, best, off);
        int   oc = __shfl_xor_sync(0xFFFFFFFFu, bc,   off);
        if (ov > best || (ov == best && oc < bc)) { best = ov; bc = oc; }
    }
    if (q == 0) {
        int ga = bid * SROWS + r;
        float sc = (obj > CONF_T) ? best : -1.0f;
        g_score[ga] = sc;
        g_cls[ga]   = (float)bc;
        unsigned int key16 = f2key(sc) >> 16;
        atomicAdd(&g_hist[key16], 1u);
        atomicAdd(&g_chunk[key16 >> 10], 1u);
    }
}

// ---------------- node 2: everything else, one persistent kernel -------------
__global__ void __launch_bounds__(MTHR, 1) k_mega(const float* __restrict__ x,
                                                  float* __restrict__ out) {
    __shared__ unsigned int       s_sufg[256];
    __shared__ int                s_c, s_g;
    __shared__ unsigned int       s_rem;
    __shared__ unsigned int       s_tb;
    __shared__ unsigned long long s_tile[MTHR];
    __shared__ float              e_y1[16][32], e_x1[16][32], e_y2[16][32], e_x2[16][32], e_ar[16][32];
    __shared__ unsigned int       s_rm[NWORDS];
    __shared__ unsigned int       s_kept[NWORDS];
    __shared__ int                s_tot[NWORDS];

    const int tid  = threadIdx.x;
    const int bid  = blockIdx.x;
    const int gid  = bid * MTHR + tid;
    const int lane = tid & 31;
    const int wid  = tid >> 5;

    // ---- A1: threshold bucket, computed redundantly by EVERY block ----
    {
        if (tid == 0) {
            unsigned int cum = 0; int c = 0; unsigned int rem = TOPK;
            for (int b = 63; b >= 0; b--) {
                unsigned int cb = g_chunk[b];
                if (cum + cb >= TOPK) { c = b; rem = TOPK - cum; break; }
                cum += cb;
            }
            s_c = c; s_rem = rem;
        }
        __syncthreads();
        int c = s_c;
        if (tid < 256) {
            unsigned int grp = 0;
#pragma unroll
            for (int k = 0; k < 4; k++) grp += g_hist[c * 1024 + tid * 4 + k];
            s_sufg[tid] = grp;
        }
        __syncthreads();
        for (int off = 1; off < 256; off <<= 1) {
            unsigned int v = 0;
            if (tid < 256 && tid + off < 256) v = s_sufg[tid + off];
            __syncthreads();
            if (tid < 256) s_sufg[tid] += v;
            __syncthreads();
        }
        unsigned int rem = s_rem;
        if (tid < 256 && s_sufg[tid] >= rem && (tid == 255 || s_sufg[tid + 1] < rem)) s_g = tid;
        __syncthreads();
        if (tid == 0) {
            int g = s_g;
            unsigned int cum = (g == 255) ? 0u : s_sufg[g + 1];
            int T = c * 1024 + g * 4;
            for (int b = g * 4 + 3; b >= g * 4; b--) {
                cum += g_hist[c * 1024 + b];
                if (cum >= rem) { T = c * 1024 + b; break; }
            }
            s_tb = (unsigned int)T;
        }
        __syncthreads();
    }

    // ---- A2: compact candidates (no barrier since threshold is local) ----
    {
        unsigned int tb = s_tb;
        for (int i = gid; i < N_ANCH; i += MTOT) {
            unsigned int k = f2key(g_score[i]);
            if ((k >> 16) >= tb) {
                unsigned int pos = atomicAdd(&g_ncand, 1u);
                if (pos < CAND_CAP)
                    g_cand[pos] = ((unsigned long long)k << 32) | (unsigned int)(~i);
            }
        }
    }
    grid_bar();

    // ---- B: segmented rank counting (blocks 0..127; 8 segments) ----
    {
        unsigned int n = g_ncand; if (n > CAND_CAP) n = CAND_CAP;
        if (bid < 128) {
            int c   = gid & (CAND_CAP - 1);
            int seg = gid >> 13;                  // 0..7
            unsigned int piece = (n + 7) >> 3;
            unsigned int lo = seg * piece;
            unsigned int hi = lo + piece; if (hi > n) hi = n;
            unsigned long long my = (c < (int)n) ? g_cand[c] : 0ULL;
            unsigned int cnt = 0;
            for (unsigned int base = lo; base < hi; base += MTHR) {
                unsigned int idx = base + tid;
                s_tile[tid] = (idx < hi) ? g_cand[idx] : 0ULL;
                __syncthreads();
                unsigned int lim = (hi - base < (unsigned)MTHR) ? (hi - base) : (unsigned)MTHR;
                for (unsigned int k = 0; k < lim; k++) cnt += (s_tile[k] > my);
                __syncthreads();
            }
            if (c < (int)n && cnt) atomicAdd(&g_rankp[c], cnt);
        }
    }
    grid_bar();

    // ---- C: scatter into sorted order + box gather; reset hist/counters ----
    {
        unsigned int n = g_ncand; if (n > CAND_CAP) n = CAND_CAP;
        if (gid < (int)n) {
            unsigned long long my = g_cand[gid];
            unsigned int rank = g_rankp[gid];
            g_rankp[gid] = 0u;
            if (rank < TOPK) {
                int a = (int)(~(unsigned int)my);
                g_top_s[rank]   = key2f((unsigned int)(my >> 32));
                g_top_idx[rank] = a;
                const float* row = x + (size_t)a * D_COLS;
                float xc = row[0], yc = row[1], w = row[2], h = row[3];
                float hh = __fmul_rn(h, 0.5f), hw = __fmul_rn(w, 0.5f);
                float y1 = __fsub_rn(yc, hh), x1 = __fsub_rn(xc, hw);
                float y2 = __fadd_rn(yc, hh), x2 = __fadd_rn(xc, hw);
                g_by1[rank] = y1; g_bx1[rank] = x1; g_by2[rank] = y2; g_bx2[rank] = x2;
                g_bar_a[rank] = __fmul_rn(__fsub_rn(y2, y1), __fsub_rn(x2, x1));
            }
        }
        if (gid < 65536) g_hist[gid] = 0u;       // safe: last hist read was in A1
        if (gid < 64)    g_chunk[gid] = 0u;
        if (gid == 0)    g_ncand = 0u;
    }
    grid_bar();

    // ---- D: dense suppression bitmask, transposed ----
    {
        int gwm = bid * 16 + wid;
        for (int g = gwm; g < 16384; g += MWARPS) {
            int rg = g >> 7;
            int w  = g & 127;
            int i  = (rg << 5) | lane;
            if (w < rg) { g_maskT[w * TOPK + i] = 0u; continue; }

            int jj = (w << 5) + lane;
            e_y1[wid][lane] = g_by1[jj]; e_x1[wid][lane] = g_bx1[jj];
            e_y2[wid][lane] = g_by2[jj]; e_x2[wid][lane] = g_bx2[jj];
            e_ar[wid][lane] = g_bar_a[jj];
            __syncwarp();

            float ry1 = g_by1[i], rx1 = g_bx1[i], ry2 = g_by2[i], rx2 = g_bx2[i];
            float rar = g_bar_a[i];
            bool  diag = (w == rg);

            unsigned int word = 0;
#pragma unroll 4
            for (int k = 0; k < 32; k++) {
                if (diag && k <= lane) continue;
                float yy1 = fmaxf(ry1, e_y1[wid][k]);
                float xx1 = fmaxf(rx1, e_x1[wid][k]);
                float yy2 = fminf(ry2, e_y2[wid][k]);
                float xx2 = fminf(rx2, e_x2[wid][k]);
                float dh  = fmaxf(__fsub_rn(yy2, yy1), 0.0f);
                float dw  = fmaxf(__fsub_rn(xx2, xx1), 0.0f);
                float it  = __fmul_rn(dh, dw);
                if (it > 0.0f) {
                    float un  = __fsub_rn(__fadd_rn(rar, e_ar[wid][k]), it);
                    float unc = fmaxf(un, 1e-9f);
                    float c   = __fmul_rn(IOU_T, unc);
                    bool  sup;
                    if (fabsf(__fsub_rn(it, c)) > 1e-4f * c) {
                        sup = (it > c);                       // far from boundary
                    } else {
                        sup = (__fdiv_rn(it, unc) > IOU_T);   // exact ref rounding
                    }
                    if (sup) word |= 1u << k;
                }
            }
            g_maskT[w * TOPK + i] = word;
            __syncwarp();
        }
    }
    grid_bar();

    // ---- E: greedy sweep with early-stop at 300 kept (block 0) ----
    if (bid == 0) {
        bool act = tid < 128;
        unsigned int init_rm = 0, acc = 0;
        const uint4* rbase = (const uint4*)g_maskT + (size_t)(act ? tid : 0) * (TOPK / 4);
        if (act) {
#pragma unroll 4
            for (int b = 0; b < 32; b++)
                if (!(g_top_s[tid * 32 + b] > -0.5f)) init_rm |= 1u << b;
        }
        unsigned int A[32], B[32];
        if (act) {
#pragma unroll
            for (int q = 0; q < 8; q++) {
                uint4 v = rbase[q];
                A[q*4+0] = v.x; A[q*4+1] = v.y; A[q*4+2] = v.z; A[q*4+3] = v.w;
            }
        }
        __syncthreads();
        int wstop = NWORDS;
#pragma unroll 1
        for (int w = 0; w < NWORDS; w++) {
            if (act && w + 1 < NWORDS) {
#pragma unroll
                for (int q = 0; q < 8; q++) {
                    uint4 v = rbase[(w + 1) * 8 + q];
                    B[q*4+0] = v.x; B[q*4+1] = v.y; B[q*4+2] = v.z; B[q*4+3] = v.w;
                }
            }
            if (tid == w) {
                unsigned int rm = init_rm | acc;
                unsigned int kept = 0;
#pragma unroll
                for (int b = 0; b < 32; b++) {
                    if (!((rm >> b) & 1u)) { kept |= 1u << b; rm |= A[b]; }
                }
                s_rm[w] = rm; s_kept[w] = kept;
                s_tot[w] = (w ? s_tot[w - 1] : 0) + __popc(kept);   // owner-only write
            }
            __syncthreads();                       // single barrier per iteration
            if (s_tot[w] >= MAX_DET) { wstop = w + 1; break; }      // uniform decision
            if (act) {
                unsigned int kk = s_kept[w];
#pragma unroll
                for (int b = 0; b < 32; b++)
                    acc |= ((kk >> b) & 1u) ? A[b] : 0u;
#pragma unroll
                for (int b = 0; b < 32; b++) A[b] = B[b];
            }
        }
        __syncthreads();
        if (tid == 0) {            // top-300: kept first (score-desc), then pad
            int cnt = 0;
            for (int w = 0; w < wstop && cnt < MAX_DET; w++) {
                unsigned int kept = s_kept[w];
                while (kept && cnt < MAX_DET) {
                    int b = __ffs(kept) - 1; kept &= kept - 1;
                    g_out_pos[cnt] = (w << 5) | b; g_out_keep[cnt] = 1; cnt++;
                }
            }
            for (int w = 0; w < wstop && cnt < MAX_DET; w++) {      // pad (full sweep only)
                unsigned int dead = s_rm[w];
                while (dead && cnt < MAX_DET) {
                    int b = __ffs(dead) - 1; dead &= dead - 1;
                    g_out_pos[cnt] = (w << 5) | b; g_out_keep[cnt] = 0; cnt++;
                }
            }
        }
    }
    grid_bar();

    // ---- F: final gather -> out (300 warps across blocks) ----
    {
        int gw = bid * 16 + wid;
        if (gw < MAX_DET) {
            int pos = g_out_pos[gw];
            int a   = g_top_idx[pos];
            const float* row = x + (size_t)a * D_COLS;
            if (lane == 0) {
                float xc = row[0], yc = row[1], w = row[2], h = row[3];
                float hh = __fmul_rn(h, 0.5f), hw = __fmul_rn(w, 0.5f);
                out[gw * 4 + 0] = __fsub_rn(yc, hh);
                out[gw * 4 + 1] = __fsub_rn(xc, hw);
                out[gw * 4 + 2] = __fadd_rn(yc, hh);
                out[gw * 4 + 3] = __fadd_rn(xc, hw);
                out[MAX_DET * 4 + gw] = g_cls[a];
                out[MAX_DET * 5 + gw] = g_out_keep[gw] ? g_top_s[pos] : -1.0f;
            }
            out[MAX_DET * 6 + gw * NM + lane] = row[5 + NC + lane];
        }
    }
}

// ---------------- launch ----------------
extern "C" void kernel_launch(void* const* d_in, const int* in_sizes, int n_in,
                              void* d_out, int out_size) {
    const float* x = (const float*)d_in[0];
    float* out = (float*)d_out;

    k_score <<<N_ANCH / SROWS, 256>>>(x);
    k_mega  <<<MBLK, MTHR>>>(x, out);
}

// round 12
// speedup vs baseline: 1.1536x; 1.1095x over previous
#include <cuda_runtime.h>
#include <cstdint>

#define N_ANCH   100800
#define D_COLS   117
#define NC       80
#define NM       32
#define TOPK     4096
#define MAX_DET  300
#define CONF_T   0.25f
#define IOU_T    0.45f
#define CAND_CAP 8192
#define NWORDS   128            // TOPK/32
#define MBLK     148
#define MTHR     512
#define MTOT     (MBLK * MTHR)  // 75776
#define MWARPS   (MBLK * 16)    // 2368
#define SROWS    64             // rows per score block
#define SF4      ((SROWS * D_COLS) / 4)   // 1872 float4 per tile

// ---------------- scratch (static __device__ — no allocation) ----------------
__device__ float              g_score[N_ANCH];
__device__ float              g_cls[N_ANCH];
__device__ unsigned int       g_hist[65536];          // zero at init; re-zeroed each run
__device__ unsigned int       g_ncand;                // zero at init; reset each run
__device__ unsigned long long g_cand[CAND_CAP];
__device__ unsigned int       g_rankp[CAND_CAP];      // zero at init; reset each run
__device__ int                g_top_idx[TOPK];
__device__ float              g_top_s[TOPK];
__device__ float              g_by1[TOPK], g_bx1[TOPK], g_by2[TOPK], g_bx2[TOPK], g_bar_a[TOPK];
__device__ unsigned int       g_maskT[NWORDS * TOPK]; // [jword][row]; lower triangle unused
__device__ int                g_out_pos[MAX_DET];
__device__ unsigned char      g_out_keep[MAX_DET];

__device__ unsigned int          g_bar_count;
__device__ volatile unsigned int g_bar_gen;

// ---------------- helpers ----------------
__device__ __forceinline__ unsigned int f2key(float f) {
    unsigned int b = __float_as_uint(f);
    return b ^ ((b >> 31) ? 0xFFFFFFFFu : 0x80000000u);
}
__device__ __forceinline__ float key2f(unsigned int k) {
    unsigned int b = (k & 0x80000000u) ? (k ^ 0x80000000u) : ~k;
    return __uint_as_float(b);
}
__device__ __forceinline__ void grid_bar() {
    __syncthreads();
    if (threadIdx.x == 0) {
        unsigned int gen = g_bar_gen;
        __threadfence();
        unsigned int t = atomicAdd(&g_bar_count, 1u);
        if (t == MBLK - 1) {
            g_bar_count = 0;
            __threadfence();
            g_bar_gen = gen + 1;
        } else {
            while (g_bar_gen == gen) { }
        }
        __threadfence();
    }
    __syncthreads();
}

// ---------------- node 1: score/class + histogram (quarter-row) --------------
__global__ void __launch_bounds__(256) k_score(const float* __restrict__ x) {
    __shared__ float tile[SROWS * D_COLS];   // 29952 B
    const int bid = blockIdx.x;
    const int tid = threadIdx.x;

    // batched tile load: 8 predicated LDG.128 in flight per thread
    const float4* src = (const float4*)(x + (size_t)bid * SROWS * D_COLS);
    float4 v[8];
#pragma unroll
    for (int k = 0; k < 8; k++) {
        int i = tid + k * 256;
        if (i < SF4) v[k] = src[i];
    }
    float4* dst4 = (float4*)tile;
#pragma unroll
    for (int k = 0; k < 8; k++) {
        int i = tid + k * 256;
        if (i < SF4) dst4[i] = v[k];
    }
    __syncthreads();

    // thread = (row, quarter): 20 classes each, then 4-lane xor reduce
    const int r = tid >> 2, q = tid & 3;
    const float* row = tile + r * D_COLS;
    float obj = row[4];

    float best = -1.0f; int bc = NC;
#pragma unroll
    for (int k = 0; k < 20; k++) {
        int c = q * 20 + k;
        float p = __fmul_rn(row[5 + c], obj);
        if (p > best) { best = p; bc = c; }     // strict > : first index wins
    }
#pragma unroll
    for (int off = 1; off <= 2; off <<= 1) {
        float ov = __shfl_xor_sync(0xFFFFFFFFu, best, off);
        int   oc = __shfl_xor_sync(0xFFFFFFFFu, bc,   off);
        if (ov > best || (ov == best && oc < bc)) { best = ov; bc = oc; }
    }
    if (q == 0) {
        int ga = bid * SROWS + r;
        float sc = (obj > CONF_T) ? best : -1.0f;
        g_score[ga] = sc;
        g_cls[ga]   = (float)bc;
        atomicAdd(&g_hist[f2key(sc) >> 16], 1u);   // single cold-bucket atomic
    }
}

// ---------------- node 2: everything else, one persistent kernel -------------
__global__ void __launch_bounds__(MTHR, 1) k_mega(const float* __restrict__ x,
                                                  float* __restrict__ out) {
    __shared__ unsigned int       s_chunkv[64];
    __shared__ unsigned int       s_sufg[256];
    __shared__ int                s_c, s_g;
    __shared__ unsigned int       s_rem;
    __shared__ unsigned int       s_tb;
    __shared__ unsigned long long s_tile[MTHR];
    __shared__ float              e_y1[16][32], e_x1[16][32], e_y2[16][32], e_x2[16][32], e_ar[16][32];
    __shared__ unsigned int       s_rm[NWORDS];
    __shared__ unsigned int       s_kept[NWORDS];
    __shared__ int                s_tot[NWORDS];

    const int tid  = threadIdx.x;
    const int bid  = blockIdx.x;
    const int gid  = bid * MTHR + tid;
    const int lane = tid & 31;
    const int wid  = tid >> 5;

    // ---- A1: threshold bucket, computed redundantly by EVERY block ----
    {
        if (tid < 64) s_chunkv[tid] = 0u;
        __syncthreads();
        // chunk sums from g_hist: MLP-8 coalesced batches (L2-broadcast)
#pragma unroll 1
        for (int base = 0; base < 128; base += 8) {
            unsigned int v[8];
#pragma unroll
            for (int j = 0; j < 8; j++) v[j] = g_hist[(base + j) * 512 + tid];
#pragma unroll
            for (int j = 0; j < 8; j++) {
                unsigned int s = v[j];
#pragma unroll
                for (int off = 16; off; off >>= 1) s += __shfl_down_sync(0xFFFFFFFFu, s, off);
                if (lane == 0) atomicAdd(&s_chunkv[(base + j) >> 1], s);
            }
        }
        __syncthreads();
        if (tid == 0) {
            unsigned int cum = 0; int c = 0; unsigned int rem = TOPK;
            for (int b = 63; b >= 0; b--) {
                unsigned int cb = s_chunkv[b];
                if (cum + cb >= TOPK) { c = b; rem = TOPK - cum; break; }
                cum += cb;
            }
            s_c = c; s_rem = rem;
        }
        __syncthreads();
        int c = s_c;
        if (tid < 256) {
            unsigned int grp = 0;
#pragma unroll
            for (int k = 0; k < 4; k++) grp += g_hist[c * 1024 + tid * 4 + k];
            s_sufg[tid] = grp;
        }
        __syncthreads();
        for (int off = 1; off < 256; off <<= 1) {
            unsigned int v = 0;
            if (tid < 256 && tid + off < 256) v = s_sufg[tid + off];
            __syncthreads();
            if (tid < 256) s_sufg[tid] += v;
            __syncthreads();
        }
        unsigned int rem = s_rem;
        if (tid < 256 && s_sufg[tid] >= rem && (tid == 255 || s_sufg[tid + 1] < rem)) s_g = tid;
        __syncthreads();
        if (tid == 0) {
            int g = s_g;
            unsigned int cum = (g == 255) ? 0u : s_sufg[g + 1];
            int T = c * 1024 + g * 4;
            for (int b = g * 4 + 3; b >= g * 4; b--) {
                cum += g_hist[c * 1024 + b];
                if (cum >= rem) { T = c * 1024 + b; break; }
            }
            s_tb = (unsigned int)T;
        }
        __syncthreads();
    }

    // ---- A2: compact candidates (no barrier; threshold is block-local) ----
    {
        unsigned int tb = s_tb;
        for (int i = gid; i < N_ANCH; i += MTOT) {
            unsigned int k = f2key(g_score[i]);
            if ((k >> 16) >= tb) {
                unsigned int pos = atomicAdd(&g_ncand, 1u);
                if (pos < CAND_CAP)
                    g_cand[pos] = ((unsigned long long)k << 32) | (unsigned int)(~i);
            }
        }
    }
    grid_bar();

    // ---- B: segmented rank counting (blocks 0..127; 8 segments) ----
    {
        unsigned int n = g_ncand; if (n > CAND_CAP) n = CAND_CAP;
        if (bid < 128) {
            int c   = gid & (CAND_CAP - 1);
            int seg = gid >> 13;                  // 0..7
            unsigned int piece = (n + 7) >> 3;
            unsigned int lo = seg * piece;
            unsigned int hi = lo + piece; if (hi > n) hi = n;
            unsigned long long my = (c < (int)n) ? g_cand[c] : 0ULL;
            unsigned int cnt = 0;
            for (unsigned int base = lo; base < hi; base += MTHR) {
                unsigned int idx = base + tid;
                s_tile[tid] = (idx < hi) ? g_cand[idx] : 0ULL;
                __syncthreads();
                unsigned int lim = (hi - base < (unsigned)MTHR) ? (hi - base) : (unsigned)MTHR;
                for (unsigned int k = 0; k < lim; k++) cnt += (s_tile[k] > my);
                __syncthreads();
            }
            if (c < (int)n && cnt) atomicAdd(&g_rankp[c], cnt);
        }
    }
    grid_bar();

    // ---- C: scatter into sorted order + box gather; reset hist/counters ----
    {
        unsigned int n = g_ncand; if (n > CAND_CAP) n = CAND_CAP;
        if (gid < (int)n) {
            unsigned long long my = g_cand[gid];
            unsigned int rank = g_rankp[gid];
            g_rankp[gid] = 0u;
            if (rank < TOPK) {
                int a = (int)(~(unsigned int)my);
                g_top_s[rank]   = key2f((unsigned int)(my >> 32));
                g_top_idx[rank] = a;
                const float* row = x + (size_t)a * D_COLS;
                float xc = row[0], yc = row[1], w = row[2], h = row[3];
                float hh = __fmul_rn(h, 0.5f), hw = __fmul_rn(w, 0.5f);
                float y1 = __fsub_rn(yc, hh), x1 = __fsub_rn(xc, hw);
                float y2 = __fadd_rn(yc, hh), x2 = __fadd_rn(xc, hw);
                g_by1[rank] = y1; g_bx1[rank] = x1; g_by2[rank] = y2; g_bx2[rank] = x2;
                g_bar_a[rank] = __fmul_rn(__fsub_rn(y2, y1), __fsub_rn(x2, x1));
            }
        }
        if (gid < 65536) g_hist[gid] = 0u;       // safe: last hist read in A1, 2 bars ago
        if (gid == 0)    g_ncand = 0u;
    }
    grid_bar();

    // ---- D: suppression bitmask, transposed, UPPER TRIANGLE ONLY ----
    {
        int gwm = bid * 16 + wid;
        for (int g = gwm; g < 16384; g += MWARPS) {
            int rg = g >> 7;
            int w  = g & 127;
            if (w < rg) continue;                 // lower triangle never read by E
            int i  = (rg << 5) | lane;

            int jj = (w << 5) + lane;
            e_y1[wid][lane] = g_by1[jj]; e_x1[wid][lane] = g_bx1[jj];
            e_y2[wid][lane] = g_by2[jj]; e_x2[wid][lane] = g_bx2[jj];
            e_ar[wid][lane] = g_bar_a[jj];
            __syncwarp();

            float ry1 = g_by1[i], rx1 = g_bx1[i], ry2 = g_by2[i], rx2 = g_bx2[i];
            float rar = g_bar_a[i];
            bool  diag = (w == rg);

            unsigned int word = 0;
#pragma unroll 4
            for (int k = 0; k < 32; k++) {
                if (diag && k <= lane) continue;
                float yy1 = fmaxf(ry1, e_y1[wid][k]);
                float xx1 = fmaxf(rx1, e_x1[wid][k]);
                float yy2 = fminf(ry2, e_y2[wid][k]);
                float xx2 = fminf(rx2, e_x2[wid][k]);
                float dh  = fmaxf(__fsub_rn(yy2, yy1), 0.0f);
                float dw  = fmaxf(__fsub_rn(xx2, xx1), 0.0f);
                float it  = __fmul_rn(dh, dw);
                if (it > 0.0f) {
                    float un  = __fsub_rn(__fadd_rn(rar, e_ar[wid][k]), it);
                    float unc = fmaxf(un, 1e-9f);
                    float c   = __fmul_rn(IOU_T, unc);
                    bool  sup;
                    if (fabsf(__fsub_rn(it, c)) > 1e-4f * c) {
                        sup = (it > c);                       // far from boundary
                    } else {
                        sup = (__fdiv_rn(it, unc) > IOU_T);   // exact ref rounding
                    }
                    if (sup) word |= 1u << k;
                }
            }
            g_maskT[w * TOPK + i] = word;
            __syncwarp();
        }
    }
    grid_bar();

    // ---- E: greedy sweep, early-stop at 300 kept, triangle-guarded loads ----
    if (bid == 0) {
        bool act = tid < 128;
        unsigned int init_rm = 0, acc = 0;
        const uint4* rbase = (const uint4*)g_maskT + (size_t)(act ? tid : 0) * (TOPK / 4);
        if (act) {
#pragma unroll 4
            for (int b = 0; b < 32; b++)
                if (!(g_top_s[tid * 32 + b] > -0.5f)) init_rm |= 1u << b;
        }
        unsigned int A[32], B[32];
        if (act) {                                 // w=0: all threads t>=0 load
#pragma unroll
            for (int q = 0; q < 8; q++) {
                uint4 v = rbase[q];
                A[q*4+0] = v.x; A[q*4+1] = v.y; A[q*4+2] = v.z; A[q*4+3] = v.w;
            }
        }
        __syncthreads();
        int wstop = NWORDS;
#pragma unroll 1
        for (int w = 0; w < NWORDS; w++) {
            bool mine = act && tid >= w;           // words t<w are structurally zero
            if (act && tid >= w + 1 && w + 1 < NWORDS) {   // prefetch w+1
#pragma unroll
                for (int q = 0; q < 8; q++) {
                    uint4 v = rbase[(w + 1) * 8 + q];
                    B[q*4+0] = v.x; B[q*4+1] = v.y; B[q*4+2] = v.z; B[q*4+3] = v.w;
                }
            }
            if (tid == w) {
                unsigned int rm = init_rm | acc;
                unsigned int kept = 0;
#pragma unroll
                for (int b = 0; b < 32; b++) {
                    if (!((rm >> b) & 1u)) { kept |= 1u << b; rm |= A[b]; }
                }
                s_rm[w] = rm; s_kept[w] = kept;
                s_tot[w] = (w ? s_tot[w - 1] : 0) + __popc(kept);   // owner-only write
            }
            __syncthreads();                       // single barrier per iteration
            if (s_tot[w] >= MAX_DET) { wstop = w + 1; break; }      // uniform decision
            if (mine) {
                unsigned int kk = s_kept[w];
#pragma unroll
                for (int b = 0; b < 32; b++)
                    acc |= ((kk >> b) & 1u) ? A[b] : 0u;
            }
            if (act && tid >= w + 1) {
#pragma unroll
                for (int b = 0; b < 32; b++) A[b] = B[b];
            }
        }
        __syncthreads();
        if (tid == 0) {            // top-300: kept first (score-desc), then pad
            int cnt = 0;
            for (int w = 0; w < wstop && cnt < MAX_DET; w++) {
                unsigned int kept = s_kept[w];
                while (kept && cnt < MAX_DET) {
                    int b = __ffs(kept) - 1; kept &= kept - 1;
                    g_out_pos[cnt] = (w << 5) | b; g_out_keep[cnt] = 1; cnt++;
                }
            }
            for (int w = 0; w < wstop && cnt < MAX_DET; w++) {      // pad (full sweep only)
                unsigned int dead = s_rm[w];
                while (dead && cnt < MAX_DET) {
                    int b = __ffs(dead) - 1; dead &= dead - 1;
                    g_out_pos[cnt] = (w << 5) | b; g_out_keep[cnt] = 0; cnt++;
                }
            }
        }
    }
    grid_bar();

    // ---- F: final gather -> out (300 warps across blocks) ----
    {
        int gw = bid * 16 + wid;
        if (gw < MAX_DET) {
            int pos = g_out_pos[gw];
            int a   = g_top_idx[pos];
            const float* row = x + (size_t)a * D_COLS;
            if (lane == 0) {
                float xc = row[0], yc = row[1], w = row[2], h = row[3];
                float hh = __fmul_rn(h, 0.5f), hw = __fmul_rn(w, 0.5f);
                out[gw * 4 + 0] = __fsub_rn(yc, hh);
                out[gw * 4 + 1] = __fsub_rn(xc, hw);
                out[gw * 4 + 2] = __fadd_rn(yc, hh);
                out[gw * 4 + 3] = __fadd_rn(xc, hw);
                out[MAX_DET * 4 + gw] = g_cls[a];
                out[MAX_DET * 5 + gw] = g_out_keep[gw] ? g_top_s[pos] : -1.0f;
            }
            out[MAX_DET * 6 + gw * NM + lane] = row[5 + NC + lane];
        }
    }
}

// ---------------- launch ----------------
extern "C" void kernel_launch(void* const* d_in, const int* in_sizes, int n_in,
                              void* d_out, int out_size) {
    const float* x = (const float*)d_in[0];
    float* out = (float*)d_out;

    k_score <<<N_ANCH / SROWS, 256>>>(x);
    k_mega  <<<MBLK, MTHR>>>(x, out);
}

// round 13
// speedup vs baseline: 1.3526x; 1.1725x over previous
#include <cuda_runtime.h>
#include <cstdint>

#define N_ANCH   100800
#define D_COLS   117
#define NC       80
#define NM       32
#define TOPK     4096
#define MAX_DET  300
#define CONF_T   0.25f
#define IOU_T    0.45f
#define CAND_CAP 8192
#define NWORDS   128            // TOPK/32
#define MBLK     148
#define MTHR     512
#define MTOT     (MBLK * MTHR)  // 75776
#define MWARPS   (MBLK * 16)    // 2368
#define SROWS    64             // rows per score block
#define SF4      ((SROWS * D_COLS) / 4)   // 1872 float4 per tile

// ---------------- scratch (static __device__ — no allocation) ----------------
__device__ float              g_score[N_ANCH];
__device__ float              g_cls[N_ANCH];
__device__ unsigned int       g_hist[65536];          // zero at init; re-zeroed each run
__device__ unsigned int       g_chunk[64];            // written fresh each run (A1a)
__device__ unsigned int       g_ncand;                // zero at init; reset each run
__device__ unsigned long long g_cand[CAND_CAP];
__device__ unsigned int       g_rankp[CAND_CAP];      // zero at init; reset each run
__device__ int                g_top_idx[TOPK];
__device__ float              g_top_s[TOPK];
__device__ float              g_by1[TOPK], g_bx1[TOPK], g_by2[TOPK], g_bx2[TOPK], g_bar_a[TOPK];
__device__ unsigned int       g_maskT[NWORDS * TOPK]; // [jword][row]; lower triangle unused
__device__ int                g_out_pos[MAX_DET];
__device__ unsigned char      g_out_keep[MAX_DET];

__device__ unsigned int          g_bar_count;
__device__ volatile unsigned int g_bar_gen;

// ---------------- helpers ----------------
__device__ __forceinline__ unsigned int f2key(float f) {
    unsigned int b = __float_as_uint(f);
    return b ^ ((b >> 31) ? 0xFFFFFFFFu : 0x80000000u);
}
__device__ __forceinline__ float key2f(unsigned int k) {
    unsigned int b = (k & 0x80000000u) ? (k ^ 0x80000000u) : ~k;
    return __uint_as_float(b);
}
__device__ __forceinline__ void grid_bar() {
    __syncthreads();
    if (threadIdx.x == 0) {
        unsigned int gen = g_bar_gen;
        __threadfence();
        unsigned int t = atomicAdd(&g_bar_count, 1u);
        if (t == MBLK - 1) {
            g_bar_count = 0;
            __threadfence();
            g_bar_gen = gen + 1;
        } else {
            while (g_bar_gen == gen) { }
        }
        __threadfence();
    }
    __syncthreads();
}

// ---------------- node 1: score/class + histogram (quarter-row) --------------
__global__ void __launch_bounds__(256) k_score(const float* __restrict__ x) {
    __shared__ float tile[SROWS * D_COLS];   // 29952 B
    const int bid = blockIdx.x;
    const int tid = threadIdx.x;

    // batched tile load: 8 predicated LDG.128 in flight per thread
    const float4* src = (const float4*)(x + (size_t)bid * SROWS * D_COLS);
    float4 v[8];
#pragma unroll
    for (int k = 0; k < 8; k++) {
        int i = tid + k * 256;
        if (i < SF4) v[k] = src[i];
    }
    float4* dst4 = (float4*)tile;
#pragma unroll
    for (int k = 0; k < 8; k++) {
        int i = tid + k * 256;
        if (i < SF4) dst4[i] = v[k];
    }
    __syncthreads();

    // thread = (row, quarter): 20 classes each, then 4-lane xor reduce
    const int r = tid >> 2, q = tid & 3;
    const float* row = tile + r * D_COLS;
    float obj = row[4];

    float best = -1.0f; int bc = NC;
#pragma unroll
    for (int k = 0; k < 20; k++) {
        int c = q * 20 + k;
        float p = __fmul_rn(row[5 + c], obj);
        if (p > best) { best = p; bc = c; }     // strict > : first index wins
    }
#pragma unroll
    for (int off = 1; off <= 2; off <<= 1) {
        float ov = __shfl_xor_sync(0xFFFFFFFFu, best, off);
        int   oc = __shfl_xor_sync(0xFFFFFFFFu, bc,   off);
        if (ov > best || (ov == best && oc < bc)) { best = ov; bc = oc; }
    }
    if (q == 0) {
        int ga = bid * SROWS + r;
        float sc = (obj > CONF_T) ? best : -1.0f;
        g_score[ga] = sc;
        g_cls[ga]   = (float)bc;
        atomicAdd(&g_hist[f2key(sc) >> 16], 1u);   // single cold-bucket atomic
    }
}

// ---------------- node 2: everything else, one persistent kernel -------------
__global__ void __launch_bounds__(MTHR, 1) k_mega(const float* __restrict__ x,
                                                  float* __restrict__ out) {
    __shared__ unsigned int       s_chunkv[64];
    __shared__ unsigned int       s_red[16];
    __shared__ unsigned int       s_sufg[256];
    __shared__ int                s_c, s_g;
    __shared__ unsigned int       s_rem;
    __shared__ unsigned int       s_tb;
    __shared__ unsigned long long s_tile[MTHR];
    __shared__ float              e_y1[16][32], e_x1[16][32], e_y2[16][32], e_x2[16][32], e_ar[16][32];
    __shared__ unsigned int       s_rm[NWORDS];
    __shared__ unsigned int       s_kept[NWORDS];
    __shared__ int                s_tot[NWORDS];

    const int tid  = threadIdx.x;
    const int bid  = blockIdx.x;
    const int gid  = bid * MTHR + tid;
    const int lane = tid & 31;
    const int wid  = tid >> 5;

    // ---- A1a: blocks 0..63 sum their own 1024-bucket chunk -> g_chunk ----
    if (bid < 64) {
        unsigned int v = g_hist[bid * 1024 + tid] + g_hist[bid * 1024 + 512 + tid];
#pragma unroll
        for (int off = 16; off; off >>= 1) v += __shfl_down_sync(0xFFFFFFFFu, v, off);
        if (lane == 0) s_red[wid] = v;
        __syncthreads();
        if (tid == 0) {
            unsigned int s = 0;
#pragma unroll
            for (int w = 0; w < 16; w++) s += s_red[w];
            g_chunk[bid] = s;
        }
    }
    grid_bar();

    // ---- A1b: threshold bucket, computed redundantly (cheap) by EVERY block ----
    {
        if (tid < 64) s_chunkv[tid] = g_chunk[tid];   // 64 parallel L2-bcast loads
        __syncthreads();
        if (tid == 0) {
            unsigned int cum = 0; int c = 0; unsigned int rem = TOPK;
            for (int b = 63; b >= 0; b--) {
                unsigned int cb = s_chunkv[b];
                if (cum + cb >= TOPK) { c = b; rem = TOPK - cum; break; }
                cum += cb;
            }
            s_c = c; s_rem = rem;
        }
        __syncthreads();
        int c = s_c;
        if (tid < 256) {
            unsigned int grp = 0;
#pragma unroll
            for (int k = 0; k < 4; k++) grp += g_hist[c * 1024 + tid * 4 + k];
            s_sufg[tid] = grp;
        }
        __syncthreads();
        for (int off = 1; off < 256; off <<= 1) {
            unsigned int v = 0;
            if (tid < 256 && tid + off < 256) v = s_sufg[tid + off];
            __syncthreads();
            if (tid < 256) s_sufg[tid] += v;
            __syncthreads();
        }
        unsigned int rem = s_rem;
        if (tid < 256 && s_sufg[tid] >= rem && (tid == 255 || s_sufg[tid + 1] < rem)) s_g = tid;
        __syncthreads();
        if (tid == 0) {
            int g = s_g;
            unsigned int cum = (g == 255) ? 0u : s_sufg[g + 1];
            int T = c * 1024 + g * 4;
            for (int b = g * 4 + 3; b >= g * 4; b--) {
                cum += g_hist[c * 1024 + b];
                if (cum >= rem) { T = c * 1024 + b; break; }
            }
            s_tb = (unsigned int)T;
        }
        __syncthreads();
    }

    // ---- A2: compact candidates (no barrier; threshold is block-local) ----
    {
        unsigned int tb = s_tb;
        for (int i = gid; i < N_ANCH; i += MTOT) {
            unsigned int k = f2key(g_score[i]);
            if ((k >> 16) >= tb) {
                unsigned int pos = atomicAdd(&g_ncand, 1u);
                if (pos < CAND_CAP)
                    g_cand[pos] = ((unsigned long long)k << 32) | (unsigned int)(~i);
            }
        }
    }
    grid_bar();

    // ---- B: segmented rank counting (blocks 0..127; 8 segments) ----
    {
        unsigned int n = g_ncand; if (n > CAND_CAP) n = CAND_CAP;
        if (bid < 128) {
            int c   = gid & (CAND_CAP - 1);
            int seg = gid >> 13;                  // 0..7
            unsigned int piece = (n + 7) >> 3;
            unsigned int lo = seg * piece;
            unsigned int hi = lo + piece; if (hi > n) hi = n;
            unsigned long long my = (c < (int)n) ? g_cand[c] : 0ULL;
            unsigned int cnt = 0;
            for (unsigned int base = lo; base < hi; base += MTHR) {
                unsigned int idx = base + tid;
                s_tile[tid] = (idx < hi) ? g_cand[idx] : 0ULL;
                __syncthreads();
                unsigned int lim = (hi - base < (unsigned)MTHR) ? (hi - base) : (unsigned)MTHR;
                for (unsigned int k = 0; k < lim; k++) cnt += (s_tile[k] > my);
                __syncthreads();
            }
            if (c < (int)n && cnt) atomicAdd(&g_rankp[c], cnt);
        }
    }
    grid_bar();

    // ---- C: scatter into sorted order + box gather; reset hist/counters ----
    {
        unsigned int n = g_ncand; if (n > CAND_CAP) n = CAND_CAP;
        if (gid < (int)n) {
            unsigned long long my = g_cand[gid];
            unsigned int rank = g_rankp[gid];
            g_rankp[gid] = 0u;
            if (rank < TOPK) {
                int a = (int)(~(unsigned int)my);
                g_top_s[rank]   = key2f((unsigned int)(my >> 32));
                g_top_idx[rank] = a;
                const float* row = x + (size_t)a * D_COLS;
                float xc = row[0], yc = row[1], w = row[2], h = row[3];
                float hh = __fmul_rn(h, 0.5f), hw = __fmul_rn(w, 0.5f);
                float y1 = __fsub_rn(yc, hh), x1 = __fsub_rn(xc, hw);
                float y2 = __fadd_rn(yc, hh), x2 = __fadd_rn(xc, hw);
                g_by1[rank] = y1; g_bx1[rank] = x1; g_by2[rank] = y2; g_bx2[rank] = x2;
                g_bar_a[rank] = __fmul_rn(__fsub_rn(y2, y1), __fsub_rn(x2, x1));
            }
        }
        if (gid < 65536) g_hist[gid] = 0u;       // safe: last hist read in A1b, 2 bars ago
        if (gid == 0)    g_ncand = 0u;
    }
    grid_bar();

    // ---- D: suppression bitmask, transposed, UPPER TRIANGLE ONLY ----
    {
        int gwm = bid * 16 + wid;
        for (int g = gwm; g < 16384; g += MWARPS) {
            int rg = g >> 7;
            int w  = g & 127;
            if (w < rg) continue;                 // lower triangle never read by E
            int i  = (rg << 5) | lane;

            int jj = (w << 5) + lane;
            e_y1[wid][lane] = g_by1[jj]; e_x1[wid][lane] = g_bx1[jj];
            e_y2[wid][lane] = g_by2[jj]; e_x2[wid][lane] = g_bx2[jj];
            e_ar[wid][lane] = g_bar_a[jj];
            __syncwarp();

            float ry1 = g_by1[i], rx1 = g_bx1[i], ry2 = g_by2[i], rx2 = g_bx2[i];
            float rar = g_bar_a[i];
            bool  diag = (w == rg);

            unsigned int word = 0;
#pragma unroll 4
            for (int k = 0; k < 32; k++) {
                if (diag && k <= lane) continue;
                float yy1 = fmaxf(ry1, e_y1[wid][k]);
                float xx1 = fmaxf(rx1, e_x1[wid][k]);
                float yy2 = fminf(ry2, e_y2[wid][k]);
                float xx2 = fminf(rx2, e_x2[wid][k]);
                float dh  = fmaxf(__fsub_rn(yy2, yy1), 0.0f);
                float dw  = fmaxf(__fsub_rn(xx2, xx1), 0.0f);
                float it  = __fmul_rn(dh, dw);
                if (it > 0.0f) {
                    float un  = __fsub_rn(__fadd_rn(rar, e_ar[wid][k]), it);
                    float unc = fmaxf(un, 1e-9f);
                    float c   = __fmul_rn(IOU_T, unc);
                    bool  sup;
                    if (fabsf(__fsub_rn(it, c)) > 1e-4f * c) {
                        sup = (it > c);                       // far from boundary
                    } else {
                        sup = (__fdiv_rn(it, unc) > IOU_T);   // exact ref rounding
                    }
                    if (sup) word |= 1u << k;
                }
            }
            g_maskT[w * TOPK + i] = word;
            __syncwarp();
        }
    }
    grid_bar();

    // ---- E: greedy sweep, early-stop at 300 kept, triangle-guarded loads ----
    if (bid == 0) {
        bool act = tid < 128;
        unsigned int init_rm = 0, acc = 0;
        const uint4* rbase = (const uint4*)g_maskT + (size_t)(act ? tid : 0) * (TOPK / 4);
        if (act) {
#pragma unroll 4
            for (int b = 0; b < 32; b++)
                if (!(g_top_s[tid * 32 + b] > -0.5f)) init_rm |= 1u << b;
        }
        unsigned int A[32], B[32];
        if (act) {                                 // w=0: all threads t>=0 load
#pragma unroll
            for (int q = 0; q < 8; q++) {
                uint4 v = rbase[q];
                A[q*4+0] = v.x; A[q*4+1] = v.y; A[q*4+2] = v.z; A[q*4+3] = v.w;
            }
        }
        __syncthreads();
        int wstop = NWORDS;
#pragma unroll 1
        for (int w = 0; w < NWORDS; w++) {
            bool mine = act && tid >= w;           // words t<w are structurally zero
            if (act && tid >= w + 1 && w + 1 < NWORDS) {   // prefetch w+1
#pragma unroll
                for (int q = 0; q < 8; q++) {
                    uint4 v = rbase[(w + 1) * 8 + q];
                    B[q*4+0] = v.x; B[q*4+1] = v.y; B[q*4+2] = v.z; B[q*4+3] = v.w;
                }
            }
            if (tid == w) {
                unsigned int rm = init_rm | acc;
                unsigned int kept = 0;
#pragma unroll
                for (int b = 0; b < 32; b++) {
                    if (!((rm >> b) & 1u)) { kept |= 1u << b; rm |= A[b]; }
                }
                s_rm[w] = rm; s_kept[w] = kept;
                s_tot[w] = (w ? s_tot[w - 1] : 0) + __popc(kept);   // owner-only write
            }
            __syncthreads();                       // single barrier per iteration
            if (s_tot[w] >= MAX_DET) { wstop = w + 1; break; }      // uniform decision
            if (mine) {
                unsigned int kk = s_kept[w];
#pragma unroll
                for (int b = 0; b < 32; b++)
                    acc |= ((kk >> b) & 1u) ? A[b] : 0u;
            }
            if (act && tid >= w + 1) {
#pragma unroll
                for (int b = 0; b < 32; b++) A[b] = B[b];
            }
        }
        __syncthreads();
        if (tid == 0) {            // top-300: kept first (score-desc), then pad
            int cnt = 0;
            for (int w = 0; w < wstop && cnt < MAX_DET; w++) {
                unsigned int kept = s_kept[w];
                while (kept && cnt < MAX_DET) {
                    int b = __ffs(kept) - 1; kept &= kept - 1;
                    g_out_pos[cnt] = (w << 5) | b; g_out_keep[cnt] = 1; cnt++;
                }
            }
            for (int w = 0; w < wstop && cnt < MAX_DET; w++) {      // pad (full sweep only)
                unsigned int dead = s_rm[w];
                while (dead && cnt < MAX_DET) {
                    int b = __ffs(dead) - 1; dead &= dead - 1;
                    g_out_pos[cnt] = (w << 5) | b; g_out_keep[cnt] = 0; cnt++;
                }
            }
        }
    }
    grid_bar();

    // ---- F: final gather -> out (300 warps across blocks) ----
    {
        int gw = bid * 16 + wid;
        if (gw < MAX_DET) {
            int pos = g_out_pos[gw];
            int a   = g_top_idx[pos];
            const float* row = x + (size_t)a * D_COLS;
            if (lane == 0) {
                float xc = row[0], yc = row[1], w = row[2], h = row[3];
                float hh = __fmul_rn(h, 0.5f), hw = __fmul_rn(w, 0.5f);
                out[gw * 4 + 0] = __fsub_rn(yc, hh);
                out[gw * 4 + 1] = __fsub_rn(xc, hw);
                out[gw * 4 + 2] = __fadd_rn(yc, hh);
                out[gw * 4 + 3] = __fadd_rn(xc, hw);
                out[MAX_DET * 4 + gw] = g_cls[a];
                out[MAX_DET * 5 + gw] = g_out_keep[gw] ? g_top_s[pos] : -1.0f;
            }
            out[MAX_DET * 6 + gw * NM + lane] = row[5 + NC + lane];
        }
    }
}

// ---------------- launch ----------------
extern "C" void kernel_launch(void* const* d_in, const int* in_sizes, int n_in,
                              void* d_out, int out_size) {
    const float* x = (const float*)d_in[0];
    float* out = (float*)d_out;

    k_score <<<N_ANCH / SROWS, 256>>>(x);
    k_mega  <<<MBLK, MTHR>>>(x, out);
}

// round 14
// speedup vs baseline: 1.4197x; 1.0496x over previous
#include <cuda_runtime.h>
#include <cstdint>

#define N_ANCH   100800
#define D_COLS   117
#define NC       80
#define NM       32
#define TOPK     4096
#define MAX_DET  300
#define CONF_T   0.25f
#define IOU_T    0.45f
#define CAND_CAP 8192
#define NWORDS   128            // TOPK/32
#define MBLK     148
#define MTHR     512
#define MTOT     (MBLK * MTHR)  // 75776
#define MWARPS   (MBLK * 16)    // 2368
#define SROWS    64             // rows per score block
#define SBLK     (N_ANCH / SROWS)         // 1575
#define SF4      ((SROWS * D_COLS) / 4)   // 1872 float4 per tile

// ---------------- scratch (static __device__ — no allocation) ----------------
__device__ float              g_score[N_ANCH];
__device__ float              g_cls[N_ANCH];
__device__ unsigned int       g_hist[65536];          // zero at init; re-zeroed each run
__device__ unsigned int       g_chunk[64];            // zero at init; reset by last score block
__device__ unsigned int       g_done;                 // score completion ticket
__device__ unsigned int       g_tb;                   // threshold bucket
__device__ unsigned int       g_ncand;                // reset each run
__device__ unsigned long long g_cand[CAND_CAP];
__device__ unsigned int       g_rankp[CAND_CAP];      // zero; reset each run
__device__ int                g_top_idx[TOPK];
__device__ float              g_top_s[TOPK];
__device__ float              g_by1[TOPK], g_bx1[TOPK], g_by2[TOPK], g_bx2[TOPK], g_bar_a[TOPK];
__device__ unsigned int       g_maskT[NWORDS * TOPK]; // [jword][row]; lower triangle unused
__device__ int                g_out_pos[MAX_DET];
__device__ unsigned char      g_out_keep[MAX_DET];

__device__ unsigned int          g_bar_count;
__device__ volatile unsigned int g_bar_gen;

// ---------------- helpers ----------------
__device__ __forceinline__ unsigned int f2key(float f) {
    unsigned int b = __float_as_uint(f);
    return b ^ ((b >> 31) ? 0xFFFFFFFFu : 0x80000000u);
}
__device__ __forceinline__ float key2f(unsigned int k) {
    unsigned int b = (k & 0x80000000u) ? (k ^ 0x80000000u) : ~k;
    return __uint_as_float(b);
}
__device__ __forceinline__ void grid_bar() {
    __syncthreads();
    if (threadIdx.x == 0) {
        unsigned int gen = g_bar_gen;
        __threadfence();
        unsigned int t = atomicAdd(&g_bar_count, 1u);
        if (t == MBLK - 1) {
            g_bar_count = 0;
            __threadfence();
            g_bar_gen = gen + 1;
        } else {
            while (g_bar_gen == gen) { }
        }
        __threadfence();
    }
    __syncthreads();
}

// ---------------- node 1: score/class + hist + (last block) threshold -------
__global__ void __launch_bounds__(256) k_score(const float* __restrict__ x) {
    __shared__ float        tile[SROWS * D_COLS];   // 29952 B
    __shared__ unsigned int s_chunk[64];
    __shared__ unsigned int s_sufg[256];
    __shared__ int          s_c, s_g, s_last;
    __shared__ unsigned int s_rem;
    const int bid = blockIdx.x;
    const int tid = threadIdx.x;

    if (tid < 64) s_chunk[tid] = 0u;

    // batched tile load: 8 predicated LDG.128 in flight per thread
    const float4* src = (const float4*)(x + (size_t)bid * SROWS * D_COLS);
    float4 v[8];
#pragma unroll
    for (int k = 0; k < 8; k++) {
        int i = tid + k * 256;
        if (i < SF4) v[k] = src[i];
    }
    float4* dst4 = (float4*)tile;
#pragma unroll
    for (int k = 0; k < 8; k++) {
        int i = tid + k * 256;
        if (i < SF4) dst4[i] = v[k];
    }
    __syncthreads();

    // thread = (row, quarter): 20 classes each, then 4-lane xor reduce
    const int r = tid >> 2, q = tid & 3;
    const float* row = tile + r * D_COLS;
    float obj = row[4];

    float best = -1.0f; int bc = NC;
#pragma unroll
    for (int k = 0; k < 20; k++) {
        int c = q * 20 + k;
        float p = __fmul_rn(row[5 + c], obj);
        if (p > best) { best = p; bc = c; }     // strict > : first index wins
    }
#pragma unroll
    for (int off = 1; off <= 2; off <<= 1) {
        float ov = __shfl_xor_sync(0xFFFFFFFFu, best, off);
        int   oc = __shfl_xor_sync(0xFFFFFFFFu, bc,   off);
        if (ov > best || (ov == best && oc < bc)) { best = ov; bc = oc; }
    }
    if (q == 0) {
        int ga = bid * SROWS + r;
        float sc = (obj > CONF_T) ? best : -1.0f;
        g_score[ga] = sc;
        g_cls[ga]   = (float)bc;
        unsigned int key16 = f2key(sc) >> 16;
        atomicAdd(&g_hist[key16], 1u);          // cold-bucket atomic
        atomicAdd(&s_chunk[key16 >> 10], 1u);   // smem chunk counter
    }
    __syncthreads();
    if (tid < 64 && s_chunk[tid]) atomicAdd(&g_chunk[tid], s_chunk[tid]);  // ~2-3 nonzero/block

    // ---- last-block ticket: compute threshold bucket here (one block) ----
    __syncthreads();
    if (tid == 0) {
        __threadfence();
        s_last = (atomicAdd(&g_done, 1u) == SBLK - 1);
    }
    __syncthreads();
    if (!s_last) return;

    if (tid == 0) {
        unsigned int cum = 0; int c = 0; unsigned int rem = TOPK;
        for (int b = 63; b >= 0; b--) {
            unsigned int cb = g_chunk[b];
            if (cum + cb >= TOPK) { c = b; rem = TOPK - cum; break; }
            cum += cb;
        }
        s_c = c; s_rem = rem;
    }
    __syncthreads();
    {
        int c = s_c;
        unsigned int grp = 0;
#pragma unroll
        for (int k = 0; k < 4; k++) grp += g_hist[c * 1024 + tid * 4 + k];
        s_sufg[tid] = grp;
        __syncthreads();
        for (int off = 1; off < 256; off <<= 1) {
            unsigned int vv = (tid + off < 256) ? s_sufg[tid + off] : 0u;
            __syncthreads();
            s_sufg[tid] += vv;
            __syncthreads();
        }
        unsigned int rem = s_rem;
        if (s_sufg[tid] >= rem && (tid == 255 || s_sufg[tid + 1] < rem)) s_g = tid;
        __syncthreads();
        if (tid == 0) {
            int g = s_g;
            unsigned int cum = (g == 255) ? 0u : s_sufg[g + 1];
            int T = c * 1024 + g * 4;
            for (int b = g * 4 + 3; b >= g * 4; b--) {
                cum += g_hist[c * 1024 + b];
                if (cum >= rem) { T = c * 1024 + b; break; }
            }
            g_tb = (unsigned int)T;
            g_done = 0u;                        // reset for next replay
        }
        if (tid < 64) g_chunk[tid] = 0u;        // reset for next replay
    }
}

// ---------------- node 2: everything else, one persistent kernel -------------
__global__ void __launch_bounds__(MTHR, 1) k_mega(const float* __restrict__ x,
                                                  float* __restrict__ out) {
    __shared__ unsigned long long s_tile[MTHR];
    __shared__ float              e_y1[16][32], e_x1[16][32], e_y2[16][32], e_x2[16][32], e_ar[16][32];
    __shared__ unsigned int       s_rm[NWORDS];
    __shared__ unsigned int       s_kept[NWORDS];
    __shared__ int                s_tot[NWORDS];

    const int tid  = threadIdx.x;
    const int bid  = blockIdx.x;
    const int gid  = bid * MTHR + tid;
    const int lane = tid & 31;
    const int wid  = tid >> 5;

    // ---- A: compact candidates (threshold precomputed by k_score) ----
    {
        unsigned int tb = g_tb;
        for (int i = gid; i < N_ANCH; i += MTOT) {
            unsigned int k = f2key(g_score[i]);
            if ((k >> 16) >= tb) {
                unsigned int pos = atomicAdd(&g_ncand, 1u);
                if (pos < CAND_CAP)
                    g_cand[pos] = ((unsigned long long)k << 32) | (unsigned int)(~i);
            }
        }
    }
    grid_bar();

    // ---- B: segmented rank counting (blocks 0..143; 9 segments; prefetch) ----
    {
        unsigned int n = g_ncand; if (n > CAND_CAP) n = CAND_CAP;
        if (gid < 9 * CAND_CAP) {                 // 144 blocks
            int c   = gid & (CAND_CAP - 1);
            int seg = gid >> 13;                  // 0..8, uniform per block
            unsigned int piece = (n + 8) / 9;
            unsigned int lo = seg * piece;
            unsigned int hi = lo + piece; if (hi > n) hi = n;
            unsigned long long my = (c < (int)n) ? g_cand[c] : 0ULL;
            unsigned int cnt = 0;
            unsigned long long v = (lo + tid < hi) ? g_cand[lo + tid] : 0ULL;
            for (unsigned int base = lo; base < hi; base += MTHR) {
                s_tile[tid] = v;
                __syncthreads();
                unsigned int nidx = base + MTHR + tid;          // prefetch next tile
                unsigned long long vn = (nidx < hi) ? g_cand[nidx] : 0ULL;
                unsigned int lim = (hi - base < (unsigned)MTHR) ? (hi - base) : (unsigned)MTHR;
                for (unsigned int k = 0; k < lim; k++) cnt += (s_tile[k] > my);
                __syncthreads();
                v = vn;
            }
            if (c < (int)n && cnt) atomicAdd(&g_rankp[c], cnt);
        }
    }
    grid_bar();

    // ---- C: scatter into sorted order + box gather; reset hist/counters ----
    {
        unsigned int n = g_ncand; if (n > CAND_CAP) n = CAND_CAP;
        if (gid < (int)n) {
            unsigned long long my = g_cand[gid];
            unsigned int rank = g_rankp[gid];
            g_rankp[gid] = 0u;
            if (rank < TOPK) {
                int a = (int)(~(unsigned int)my);
                g_top_s[rank]   = key2f((unsigned int)(my >> 32));
                g_top_idx[rank] = a;
                const float* row = x + (size_t)a * D_COLS;
                float xc = row[0], yc = row[1], w = row[2], h = row[3];
                float hh = __fmul_rn(h, 0.5f), hw = __fmul_rn(w, 0.5f);
                float y1 = __fsub_rn(yc, hh), x1 = __fsub_rn(xc, hw);
                float y2 = __fadd_rn(yc, hh), x2 = __fadd_rn(xc, hw);
                g_by1[rank] = y1; g_bx1[rank] = x1; g_by2[rank] = y2; g_bx2[rank] = x2;
                g_bar_a[rank] = __fmul_rn(__fsub_rn(y2, y1), __fsub_rn(x2, x1));
            }
        }
        if (gid < 65536) g_hist[gid] = 0u;       // last hist read was in k_score
        if (gid == 0)    g_ncand = 0u;
    }
    grid_bar();

    // ---- D: suppression bitmask, transposed, UPPER TRIANGLE ONLY ----
    {
        int gwm = bid * 16 + wid;
        for (int g = gwm; g < 16384; g += MWARPS) {
            int rg = g >> 7;
            int w  = g & 127;
            if (w < rg) continue;                 // lower triangle never read by E
            int i  = (rg << 5) | lane;

            int jj = (w << 5) + lane;
            e_y1[wid][lane] = g_by1[jj]; e_x1[wid][lane] = g_bx1[jj];
            e_y2[wid][lane] = g_by2[jj]; e_x2[wid][lane] = g_bx2[jj];
            e_ar[wid][lane] = g_bar_a[jj];
            __syncwarp();

            float ry1 = g_by1[i], rx1 = g_bx1[i], ry2 = g_by2[i], rx2 = g_bx2[i];
            float rar = g_bar_a[i];
            bool  diag = (w == rg);

            unsigned int word = 0;
#pragma unroll 4
            for (int k = 0; k < 32; k++) {
                if (diag && k <= lane) continue;
                float yy1 = fmaxf(ry1, e_y1[wid][k]);
                float xx1 = fmaxf(rx1, e_x1[wid][k]);
                float yy2 = fminf(ry2, e_y2[wid][k]);
                float xx2 = fminf(rx2, e_x2[wid][k]);
                float dh  = fmaxf(__fsub_rn(yy2, yy1), 0.0f);
                float dw  = fmaxf(__fsub_rn(xx2, xx1), 0.0f);
                float it  = __fmul_rn(dh, dw);
                if (it > 0.0f) {
                    float un  = __fsub_rn(__fadd_rn(rar, e_ar[wid][k]), it);
                    float unc = fmaxf(un, 1e-9f);
                    float c   = __fmul_rn(IOU_T, unc);
                    bool  sup;
                    if (fabsf(__fsub_rn(it, c)) > 1e-4f * c) {
                        sup = (it > c);                       // far from boundary
                    } else {
                        sup = (__fdiv_rn(it, unc) > IOU_T);   // exact ref rounding
                    }
                    if (sup) word |= 1u << k;
                }
            }
            g_maskT[w * TOPK + i] = word;
            __syncwarp();
        }
    }
    grid_bar();

    // ---- E: greedy sweep, paired words (1 block barrier / 2 words) ----
    if (bid == 0) {
        bool act = tid < 128;
        unsigned int init_rm = 0, acc = 0;
        const uint4* rbase = (const uint4*)g_maskT + (size_t)(act ? tid : 0) * (TOPK / 4);
        if (act) {
#pragma unroll 4
            for (int b = 0; b < 32; b++)
                if (!(g_top_s[tid * 32 + b] > -0.5f)) init_rm |= 1u << b;
        }
        unsigned int A[32], B[32];
        if (act) {                                // A = rows of word 0 (all columns valid)
#pragma unroll
            for (int q2 = 0; q2 < 8; q2++) {
                uint4 v = rbase[q2];
                A[q2*4+0] = v.x; A[q2*4+1] = v.y; A[q2*4+2] = v.z; A[q2*4+3] = v.w;
            }
        }
        if (act && tid >= 1) {                    // B = rows of word 1 (cols >= 1 valid)
#pragma unroll
            for (int q2 = 0; q2 < 8; q2++) {
                uint4 v = rbase[8 + q2];
                B[q2*4+0] = v.x; B[q2*4+1] = v.y; B[q2*4+2] = v.z; B[q2*4+3] = v.w;
            }
        }
        __syncthreads();
        int wstop = NWORDS;
#pragma unroll 1
        for (int p = 0; p < NWORDS / 2; p++) {
            int w0 = 2 * p, w1 = w0 + 1;
            if (tid == w0) {
                unsigned int rm = init_rm | acc;
                unsigned int kept = 0;
#pragma unroll
                for (int b = 0; b < 32; b++) {
                    if (!((rm >> b) & 1u)) { kept |= 1u << b; rm |= A[b]; }
                }
                s_rm[w0] = rm; s_kept[w0] = kept;
                s_tot[w0] = (w0 ? s_tot[w0 - 1] : 0) + __popc(kept);
            }
            __syncwarp();                          // owners w0,w1 share a warp
            if (tid == w1) {
                unsigned int k0 = s_kept[w0];
                unsigned int rm = init_rm | acc;
#pragma unroll
                for (int b = 0; b < 32; b++)       // word-w0 kept rows hit column w1 via A
                    rm |= ((k0 >> b) & 1u) ? A[b] : 0u;
                unsigned int kept = 0;
#pragma unroll
                for (int b = 0; b < 32; b++) {
                    if (!((rm >> b) & 1u)) { kept |= 1u << b; rm |= B[b]; }
                }
                s_rm[w1] = rm; s_kept[w1] = kept;
                s_tot[w1] = s_tot[w0] + __popc(kept);
            }
            __syncthreads();                       // ONE block barrier per pair
            if (s_tot[w1] >= MAX_DET) { wstop = w1 + 1; break; }
            {
                unsigned int k0 = s_kept[w0], k1 = s_kept[w1];
                if (act && tid >= w0) {
#pragma unroll
                    for (int b = 0; b < 32; b++) acc |= ((k0 >> b) & 1u) ? A[b] : 0u;
                }
                if (act && tid >= w1) {
#pragma unroll
                    for (int b = 0; b < 32; b++) acc |= ((k1 >> b) & 1u) ? B[b] : 0u;
                }
            }
            if (p + 1 < NWORDS / 2) {              // reload pair p+1
                if (act && tid >= w0 + 2) {
#pragma unroll
                    for (int q2 = 0; q2 < 8; q2++) {
                        uint4 v = rbase[(w0 + 2) * 8 + q2];
                        A[q2*4+0] = v.x; A[q2*4+1] = v.y; A[q2*4+2] = v.z; A[q2*4+3] = v.w;
                    }
                }
                if (act && tid >= w1 + 2) {
#pragma unroll
                    for (int q2 = 0; q2 < 8; q2++) {
                        uint4 v = rbase[(w1 + 2) * 8 + q2];
                        B[q2*4+0] = v.x; B[q2*4+1] = v.y; B[q2*4+2] = v.z; B[q2*4+3] = v.w;
                    }
                }
            }
        }
        __syncthreads();
        if (tid == 0) {            // top-300: kept first (score-desc), then pad
            int cnt = 0;
            for (int w = 0; w < wstop && cnt < MAX_DET; w++) {
                unsigned int kept = s_kept[w];
                while (kept && cnt < MAX_DET) {
                    int b = __ffs(kept) - 1; kept &= kept - 1;
                    g_out_pos[cnt] = (w << 5) | b; g_out_keep[cnt] = 1; cnt++;
                }
            }
            for (int w = 0; w < wstop && cnt < MAX_DET; w++) {      // pad (full sweep only)
                unsigned int dead = s_rm[w];
                while (dead && cnt < MAX_DET) {
                    int b = __ffs(dead) - 1; dead &= dead - 1;
                    g_out_pos[cnt] = (w << 5) | b; g_out_keep[cnt] = 0; cnt++;
                }
            }
        }
    }
    grid_bar();

    // ---- F: final gather -> out (300 warps across blocks) ----
    {
        int gw = bid * 16 + wid;
        if (gw < MAX_DET) {
            int pos = g_out_pos[gw];
            int a   = g_top_idx[pos];
            const float* row = x + (size_t)a * D_COLS;
            if (lane == 0) {
                float xc = row[0], yc = row[1], w = row[2], h = row[3];
                float hh = __fmul_rn(h, 0.5f), hw = __fmul_rn(w, 0.5f);
                out[gw * 4 + 0] = __fsub_rn(yc, hh);
                out[gw * 4 + 1] = __fsub_rn(xc, hw);
                out[gw * 4 + 2] = __fadd_rn(yc, hh);
                out[gw * 4 + 3] = __fadd_rn(xc, hw);
                out[MAX_DET * 4 + gw] = g_cls[a];
                out[MAX_DET * 5 + gw] = g_out_keep[gw] ? g_top_s[pos] : -1.0f;
            }
            out[MAX_DET * 6 + gw * NM + lane] = row[5 + NC + lane];
        }
    }
}

// ---------------- launch ----------------
extern "C" void kernel_launch(void* const* d_in, const int* in_sizes, int n_in,
                              void* d_out, int out_size) {
    const float* x = (const float*)d_in[0];
    float* out = (float*)d_out;

    k_score <<<SBLK, 256>>>(x);
    k_mega  <<<MBLK, MTHR>>>(x, out);
}

// round 15
// speedup vs baseline: 1.4221x; 1.0017x over previous
#include <cuda_runtime.h>
#include <cstdint>

#define N_ANCH   100800
#define D_COLS   117
#define NC       80
#define NM       32
#define TOPK     4096
#define MAX_DET  300
#define CONF_T   0.25f
#define IOU_T    0.45f
#define CAND_CAP 8192
#define NWORDS   128            // TOPK/32
#define MBLK     148
#define MTHR     1024
#define MTOT     (MBLK * MTHR)  // 151552
#define MWARPS   (MBLK * 32)    // 4736
#define SROWS    64             // rows per score block
#define SBLK     (N_ANCH / SROWS)         // 1575
#define SF4      ((SROWS * D_COLS) / 4)   // 1872 float4 per tile

// ---------------- scratch (static __device__ — no allocation) ----------------
__device__ float              g_score[N_ANCH];
__device__ float              g_cls[N_ANCH];
__device__ unsigned int       g_hist[65536];          // zero at init; re-zeroed each run
__device__ unsigned int       g_chunk[64];            // reset by last score block
__device__ unsigned int       g_done;                 // score completion ticket
__device__ unsigned int       g_tb;                   // threshold bucket
__device__ unsigned int       g_ncand;                // reset each run
__device__ unsigned long long g_cand[CAND_CAP];
__device__ unsigned int       g_rankp[CAND_CAP];      // zero; reset each run
__device__ int                g_top_idx[TOPK];
__device__ float              g_top_s[TOPK];
__device__ float              g_by1[TOPK], g_bx1[TOPK], g_by2[TOPK], g_bx2[TOPK], g_bar_a[TOPK];
__device__ unsigned int       g_maskT[NWORDS * TOPK]; // [jword][row]; lower triangle unused
__device__ int                g_out_pos[MAX_DET];
__device__ unsigned char      g_out_keep[MAX_DET];

__device__ unsigned int          g_bar_count;
__device__ volatile unsigned int g_bar_gen;

// ---------------- helpers ----------------
__device__ __forceinline__ unsigned int f2key(float f) {
    unsigned int b = __float_as_uint(f);
    return b ^ ((b >> 31) ? 0xFFFFFFFFu : 0x80000000u);
}
__device__ __forceinline__ float key2f(unsigned int k) {
    unsigned int b = (k & 0x80000000u) ? (k ^ 0x80000000u) : ~k;
    return __uint_as_float(b);
}
__device__ __forceinline__ void grid_bar() {
    __syncthreads();
    if (threadIdx.x == 0) {
        unsigned int gen = g_bar_gen;
        __threadfence();
        unsigned int t = atomicAdd(&g_bar_count, 1u);
        if (t == MBLK - 1) {
            g_bar_count = 0;
            __threadfence();
            g_bar_gen = gen + 1;
        } else {
            while (g_bar_gen == gen) { }
        }
        __threadfence();
    }
    __syncthreads();
}

// ---------------- node 1: score/class + hist + (last block) threshold -------
__global__ void __launch_bounds__(256) k_score(const float* __restrict__ x) {
    __shared__ float        tile[SROWS * D_COLS];   // 29952 B
    __shared__ unsigned int s_chunk[64];
    __shared__ unsigned int s_sufg[256];
    __shared__ int          s_c, s_g, s_last;
    __shared__ unsigned int s_rem;
    const int bid = blockIdx.x;
    const int tid = threadIdx.x;

    if (tid < 64) s_chunk[tid] = 0u;

    // batched tile load: 8 predicated LDG.128 in flight per thread
    const float4* src = (const float4*)(x + (size_t)bid * SROWS * D_COLS);
    float4 v[8];
#pragma unroll
    for (int k = 0; k < 8; k++) {
        int i = tid + k * 256;
        if (i < SF4) v[k] = src[i];
    }
    float4* dst4 = (float4*)tile;
#pragma unroll
    for (int k = 0; k < 8; k++) {
        int i = tid + k * 256;
        if (i < SF4) dst4[i] = v[k];
    }
    __syncthreads();

    // thread = (row, quarter): 20 classes each, then 4-lane xor reduce
    const int r = tid >> 2, q = tid & 3;
    const float* row = tile + r * D_COLS;
    float obj = row[4];

    float best = -1.0f; int bc = NC;
#pragma unroll
    for (int k = 0; k < 20; k++) {
        int c = q * 20 + k;
        float p = __fmul_rn(row[5 + c], obj);
        if (p > best) { best = p; bc = c; }     // strict > : first index wins
    }
#pragma unroll
    for (int off = 1; off <= 2; off <<= 1) {
        float ov = __shfl_xor_sync(0xFFFFFFFFu, best, off);
        int   oc = __shfl_xor_sync(0xFFFFFFFFu, bc,   off);
        if (ov > best || (ov == best && oc < bc)) { best = ov; bc = oc; }
    }
    if (q == 0) {
        int ga = bid * SROWS + r;
        float sc = (obj > CONF_T) ? best : -1.0f;
        g_score[ga] = sc;
        g_cls[ga]   = (float)bc;
        unsigned int key16 = f2key(sc) >> 16;
        atomicAdd(&g_hist[key16], 1u);          // cold-bucket atomic
        atomicAdd(&s_chunk[key16 >> 10], 1u);   // smem chunk counter
    }
    __syncthreads();
    if (tid < 64 && s_chunk[tid]) atomicAdd(&g_chunk[tid], s_chunk[tid]);

    // ---- last-block ticket: compute threshold bucket here (one block) ----
    __syncthreads();
    if (tid == 0) {
        __threadfence();
        s_last = (atomicAdd(&g_done, 1u) == SBLK - 1);
    }
    __syncthreads();
    if (!s_last) return;

    if (tid == 0) {
        unsigned int cum = 0; int c = 0; unsigned int rem = TOPK;
        for (int b = 63; b >= 0; b--) {
            unsigned int cb = g_chunk[b];
            if (cum + cb >= TOPK) { c = b; rem = TOPK - cum; break; }
            cum += cb;
        }
        s_c = c; s_rem = rem;
    }
    __syncthreads();
    {
        int c = s_c;
        unsigned int grp = 0;
#pragma unroll
        for (int k = 0; k < 4; k++) grp += g_hist[c * 1024 + tid * 4 + k];
        s_sufg[tid] = grp;
        __syncthreads();
        for (int off = 1; off < 256; off <<= 1) {
            unsigned int vv = (tid + off < 256) ? s_sufg[tid + off] : 0u;
            __syncthreads();
            s_sufg[tid] += vv;
            __syncthreads();
        }
        unsigned int rem = s_rem;
        if (s_sufg[tid] >= rem && (tid == 255 || s_sufg[tid + 1] < rem)) s_g = tid;
        __syncthreads();
        if (tid == 0) {
            int g = s_g;
            unsigned int cum = (g == 255) ? 0u : s_sufg[g + 1];
            int T = c * 1024 + g * 4;
            for (int b = g * 4 + 3; b >= g * 4; b--) {
                cum += g_hist[c * 1024 + b];
                if (cum >= rem) { T = c * 1024 + b; break; }
            }
            g_tb = (unsigned int)T;
            g_done = 0u;                        // reset for next replay
        }
        if (tid < 64) g_chunk[tid] = 0u;        // reset for next replay
    }
}

// ---------------- node 2: everything else, one persistent kernel -------------
__global__ void __launch_bounds__(MTHR, 1) k_mega(const float* __restrict__ x,
                                                  float* __restrict__ out) {
    __shared__ unsigned long long s_tile[MTHR];                        // 8 KB (B)
    __shared__ float e_y1[32][32], e_x1[32][32], e_y2[32][32], e_x2[32][32], e_ar[32][32]; // 20KB (D)
    __shared__ unsigned int       s_rm[NWORDS];
    __shared__ unsigned int       s_kept[NWORDS];
    __shared__ int                s_tot[NWORDS];

    const int tid  = threadIdx.x;
    const int bid  = blockIdx.x;
    const int gid  = bid * MTHR + tid;
    const int lane = tid & 31;
    const int wid  = tid >> 5;

    // ---- A: compact candidates (threshold precomputed by k_score) ----
    if (gid < N_ANCH) {
        unsigned int tb = g_tb;
        unsigned int k = f2key(g_score[gid]);
        if ((k >> 16) >= tb) {
            unsigned int pos = atomicAdd(&g_ncand, 1u);
            if (pos < CAND_CAP)
                g_cand[pos] = ((unsigned long long)k << 32) | (unsigned int)(~gid);
        }
    }
    grid_bar();

    // ---- B: segmented rank counting (blocks 0..127; 16 segments; unrolled) --
    {
        unsigned int n = g_ncand; if (n > CAND_CAP) n = CAND_CAP;
        if (gid < 16 * CAND_CAP) {                // 128 blocks
            int c   = gid & (CAND_CAP - 1);
            int seg = gid >> 13;                  // 0..15, uniform per block
            unsigned int piece = (n + 15) >> 4;
            unsigned int lo = seg * piece;
            unsigned int hi = lo + piece; if (hi > n) hi = n;
            unsigned long long my = (c < (int)n) ? g_cand[c] : 0ULL;
            unsigned int cnt = 0;
            for (unsigned int base = lo; base < hi; base += MTHR) {
                unsigned int idx = base + tid;
                s_tile[tid] = (idx < hi) ? g_cand[idx] : 0ULL;
                __syncthreads();
                unsigned int lim = (hi - base < (unsigned)MTHR) ? (hi - base) : (unsigned)MTHR;
                unsigned int c0 = 0, c1 = 0, c2 = 0, c3 = 0, k = 0;
                for (; k + 4 <= lim; k += 4) {    // 4 independent LDS chains
                    c0 += (s_tile[k]     > my);
                    c1 += (s_tile[k + 1] > my);
                    c2 += (s_tile[k + 2] > my);
                    c3 += (s_tile[k + 3] > my);
                }
                for (; k < lim; k++) c0 += (s_tile[k] > my);
                cnt += c0 + c1 + c2 + c3;
                __syncthreads();
            }
            if (c < (int)n && cnt) atomicAdd(&g_rankp[c], cnt);
        }
    }
    grid_bar();

    // ---- C: scatter into sorted order + box gather; reset hist/counters ----
    {
        unsigned int n = g_ncand; if (n > CAND_CAP) n = CAND_CAP;
        if (gid < (int)n) {
            unsigned long long my = g_cand[gid];
            unsigned int rank = g_rankp[gid];
            g_rankp[gid] = 0u;
            if (rank < TOPK) {
                int a = (int)(~(unsigned int)my);
                g_top_s[rank]   = key2f((unsigned int)(my >> 32));
                g_top_idx[rank] = a;
                const float* row = x + (size_t)a * D_COLS;
                float xc = row[0], yc = row[1], w = row[2], h = row[3];
                float hh = __fmul_rn(h, 0.5f), hw = __fmul_rn(w, 0.5f);
                float y1 = __fsub_rn(yc, hh), x1 = __fsub_rn(xc, hw);
                float y2 = __fadd_rn(yc, hh), x2 = __fadd_rn(xc, hw);
                g_by1[rank] = y1; g_bx1[rank] = x1; g_by2[rank] = y2; g_bx2[rank] = x2;
                g_bar_a[rank] = __fmul_rn(__fsub_rn(y2, y1), __fsub_rn(x2, x1));
            }
        }
        if (gid < 65536) g_hist[gid] = 0u;       // last hist read was in k_score
        if (gid == 0)    g_ncand = 0u;
    }
    grid_bar();

    // ---- D: suppression bitmask, transposed, UPPER TRIANGLE ONLY ----
    {
        int gwm = bid * 32 + wid;
        for (int g = gwm; g < 16384; g += MWARPS) {
            int rg = g >> 7;
            int w  = g & 127;
            if (w < rg) continue;                 // lower triangle never read by E
            int i  = (rg << 5) | lane;

            int jj = (w << 5) + lane;
            e_y1[wid][lane] = g_by1[jj]; e_x1[wid][lane] = g_bx1[jj];
            e_y2[wid][lane] = g_by2[jj]; e_x2[wid][lane] = g_bx2[jj];
            e_ar[wid][lane] = g_bar_a[jj];
            __syncwarp();

            float ry1 = g_by1[i], rx1 = g_bx1[i], ry2 = g_by2[i], rx2 = g_bx2[i];
            float rar = g_bar_a[i];
            bool  diag = (w == rg);

            unsigned int word = 0;
#pragma unroll 4
            for (int k = 0; k < 32; k++) {
                if (diag && k <= lane) continue;
                float yy1 = fmaxf(ry1, e_y1[wid][k]);
                float xx1 = fmaxf(rx1, e_x1[wid][k]);
                float yy2 = fminf(ry2, e_y2[wid][k]);
                float xx2 = fminf(rx2, e_x2[wid][k]);
                float dh  = fmaxf(__fsub_rn(yy2, yy1), 0.0f);
                float dw  = fmaxf(__fsub_rn(xx2, xx1), 0.0f);
                float it  = __fmul_rn(dh, dw);
                if (it > 0.0f) {
                    float un  = __fsub_rn(__fadd_rn(rar, e_ar[wid][k]), it);
                    float unc = fmaxf(un, 1e-9f);
                    float c   = __fmul_rn(IOU_T, unc);
                    bool  sup;
                    if (fabsf(__fsub_rn(it, c)) > 1e-4f * c) {
                        sup = (it > c);                       // far from boundary
                    } else {
                        sup = (__fdiv_rn(it, unc) > IOU_T);   // exact ref rounding
                    }
                    if (sup) word |= 1u << k;
                }
            }
            g_maskT[w * TOPK + i] = word;
            __syncwarp();
        }
    }
    grid_bar();

    // ---- E: greedy sweep, early-stop at 300 kept, single-buffer (block 0) ---
    if (bid == 0) {
        bool act = tid < 128;
        unsigned int init_rm = 0, acc = 0;
        const uint4* rbase = (const uint4*)g_maskT + (size_t)(act ? tid : 0) * (TOPK / 4);
        if (act) {
#pragma unroll 4
            for (int b = 0; b < 32; b++)
                if (!(g_top_s[tid * 32 + b] > -0.5f)) init_rm |= 1u << b;
        }
        int wstop = NWORDS;
#pragma unroll 1
        for (int w = 0; w < NWORDS; w++) {
            unsigned int A[32];
            bool mine = act && tid >= w;           // words t<w are structurally zero
            if (mine) {
#pragma unroll
                for (int q = 0; q < 8; q++) {
                    uint4 v = rbase[w * 8 + q];
                    A[q*4+0] = v.x; A[q*4+1] = v.y; A[q*4+2] = v.z; A[q*4+3] = v.w;
                }
            }
            if (tid == w) {
                unsigned int rm = init_rm | acc;
                unsigned int kept = 0;
#pragma unroll
                for (int b = 0; b < 32; b++) {
                    if (!((rm >> b) & 1u)) { kept |= 1u << b; rm |= A[b]; }
                }
                s_rm[w] = rm; s_kept[w] = kept;
                s_tot[w] = (w ? s_tot[w - 1] : 0) + __popc(kept);   // owner-only write
            }
            __syncthreads();                       // single barrier per word
            if (s_tot[w] >= MAX_DET) { wstop = w + 1; break; }      // uniform decision
            if (mine) {
                unsigned int kk = s_kept[w];
#pragma unroll
                for (int b = 0; b < 32; b++)
                    acc |= ((kk >> b) & 1u) ? A[b] : 0u;
            }
        }
        __syncthreads();
        if (tid == 0) {            // top-300: kept first (score-desc), then pad
            int cnt = 0;
            for (int w = 0; w < wstop && cnt < MAX_DET; w++) {
                unsigned int kept = s_kept[w];
                while (kept && cnt < MAX_DET) {
                    int b = __ffs(kept) - 1; kept &= kept - 1;
                    g_out_pos[cnt] = (w << 5) | b; g_out_keep[cnt] = 1; cnt++;
                }
            }
            for (int w = 0; w < wstop && cnt < MAX_DET; w++) {      // pad (full sweep only)
                unsigned int dead = s_rm[w];
                while (dead && cnt < MAX_DET) {
                    int b = __ffs(dead) - 1; dead &= dead - 1;
                    g_out_pos[cnt] = (w << 5) | b; g_out_keep[cnt] = 0; cnt++;
                }
            }
        }
    }
    grid_bar();

    // ---- F: final gather -> out (300 warps across blocks) ----
    {
        int gw = bid * 32 + wid;
        if (gw < MAX_DET) {
            int pos = g_out_pos[gw];
            int a   = g_top_idx[pos];
            const float* row = x + (size_t)a * D_COLS;
            if (lane == 0) {
                float xc = row[0], yc = row[1], w = row[2], h = row[3];
                float hh = __fmul_rn(h, 0.5f), hw = __fmul_rn(w, 0.5f);
                out[gw * 4 + 0] = __fsub_rn(yc, hh);
                out[gw * 4 + 1] = __fsub_rn(xc, hw);
                out[gw * 4 + 2] = __fadd_rn(yc, hh);
                out[gw * 4 + 3] = __fadd_rn(xc, hw);
                out[MAX_DET * 4 + gw] = g_cls[a];
                out[MAX_DET * 5 + gw] = g_out_keep[gw] ? g_top_s[pos] : -1.0f;
            }
            out[MAX_DET * 6 + gw * NM + lane] = row[5 + NC + lane];
        }
    }
}

// ---------------- launch ----------------
extern "C" void kernel_launch(void* const* d_in, const int* in_sizes, int n_in,
                              void* d_out, int out_size) {
    const float* x = (const float*)d_in[0];
    float* out = (float*)d_out;

    k_score <<<SBLK, 256>>>(x);
    k_mega  <<<MBLK, MTHR>>>(x, out);
}